// round 1
// baseline (speedup 1.0000x reference)
#include <cuda_runtime.h>
#include <math.h>

// ---------------------------------------------------------------------------
// LocalAttention: conv3x3(512->768)+ReLU -> windowed attention (18 win x 4
// heads, L=1024, d=64, softmax over keys) -> conv3x3(256->512) + residual.
//
// Scratch (device globals, no allocation):
//   g_k  [72][64][1024]  keys,    c-major
//   g_q  [72][64][1024]  queries, c-major
//   g_vt [72][1024][64]  values,  i-major (transposed for PV gemm)
//   g_att  [72][1024 j][1024 i]  raw scores (softmax axis contiguous)
//   g_att2 [72][1024 i][1024 j]  softmaxed, transposed for PV gemm
//   g_o  [2][256][96][96]        attention output in spatial layout
// ---------------------------------------------------------------------------

__device__ float g_k [72 * 64 * 1024];
__device__ float g_q [72 * 64 * 1024];
__device__ float g_vt[72 * 1024 * 64];
__device__ float g_att [72 * 1024 * 1024];
__device__ float g_att2[72 * 1024 * 1024];
__device__ float g_o [2 * 256 * 96 * 96];

// ---------------------------------------------------------------------------
// Conv 3x3, pad 1. Block computes 64 output channels x (4 rows x 32 cols).
// 256 threads: 16 co-groups x 16 px-groups; each thread 4 co x 8 px.
// MODE 0: in=x (CIN=512), epilogue: +bias, ReLU, scatter into packed K/Q/V.
// MODE 1: in=g_o (CIN=256), epilogue: +bias, +residual(x), write d_out.
// ---------------------------------------------------------------------------
template <int CIN_, int MODE>
__global__ __launch_bounds__(256) void conv3x3_kernel(
    const float* __restrict__ xin,
    const float* __restrict__ W,
    const float* __restrict__ bias,
    const float* __restrict__ resid,
    float* __restrict__ out)
{
    const float* in = (MODE == 0) ? xin : g_o;
    const int IC = CIN_;

    const int b    = blockIdx.z;
    const int co0  = blockIdx.y * 64;
    const int tile = blockIdx.x;       // 72 tiles: 24 row-bands x 3 col-bands
    const int r0 = (tile / 3) * 4;
    const int c0 = (tile % 3) * 32;

    __shared__ float s_in[8 * 6 * 34];     // 8 ci x (4+2) rows x (32+2) cols
    __shared__ float s_w [64 * 73];        // 64 co x 72 (pad to 73)

    const int tid = threadIdx.x;
    const int cg  = tid >> 4;              // co group 0..15 (4 co each)
    const int pg  = tid & 15;              // pixel group 0..15
    const int pr  = pg >> 2;               // row within tile 0..3
    const int pc  = (pg & 3) * 8;          // col base 0,8,16,24

    float acc[4][8];
#pragma unroll
    for (int c = 0; c < 4; c++)
#pragma unroll
        for (int j = 0; j < 8; j++) acc[c][j] = 0.f;

    for (int ci0 = 0; ci0 < IC; ci0 += 8) {
        // --- load weights: 64 co x 72 contiguous floats each
#pragma unroll
        for (int t = 0; t < 18; t++) {
            int idx = tid + t * 256;                 // 18*256 = 4608 = 64*72
            int co = idx / 72, k = idx % 72;
            s_w[co * 73 + k] = W[(co0 + co) * IC * 9 + ci0 * 9 + k];
        }
        // --- load input patch with zero halo
        for (int idx = tid; idx < 8 * 204; idx += 256) {
            int ci  = idx / 204;
            int rem = idx % 204;
            int r = rem / 34, cx = rem % 34;
            int gh = r0 - 1 + r, gw = c0 - 1 + cx;
            float v = 0.f;
            if (gh >= 0 && gh < 96 && gw >= 0 && gw < 96)
                v = in[((b * IC + ci0 + ci) * 96 + gh) * 96 + gw];
            s_in[(ci * 6 + r) * 34 + cx] = v;
        }
        __syncthreads();

#pragma unroll 1
        for (int ci = 0; ci < 8; ci++) {
#pragma unroll
            for (int kh = 0; kh < 3; kh++) {
                float xr[10];
                const float* rowp = &s_in[(ci * 6 + pr + kh) * 34 + pc];
#pragma unroll
                for (int t = 0; t < 10; t++) xr[t] = rowp[t];
#pragma unroll
                for (int kw = 0; kw < 3; kw++) {
                    float wv[4];
#pragma unroll
                    for (int c = 0; c < 4; c++)
                        wv[c] = s_w[(cg * 4 + c) * 73 + ci * 9 + kh * 3 + kw];
#pragma unroll
                    for (int c = 0; c < 4; c++)
#pragma unroll
                        for (int j = 0; j < 8; j++)
                            acc[c][j] = fmaf(wv[c], xr[j + kw], acc[c][j]);
                }
            }
        }
        __syncthreads();
    }

    if (MODE == 0) {
        // co0 is a multiple of 64 -> (part, head) uniform per block.
        const int part = co0 >> 8;             // 0=K, 1=V, 2=Q
        const int hh   = (co0 >> 6) & 3;       // head
        const int mm = (b * 9 + (r0 >> 5) * 3 + (c0 >> 5)) * 4 + hh;
        const int lb = ((r0 + pr) & 31) * 32 + pc;   // c0 multiple of 32
#pragma unroll
        for (int c = 0; c < 4; c++) {
            int cc = cg * 4 + c;
            float bv = bias[co0 + cc];
#pragma unroll
            for (int j = 0; j < 8; j++) {
                float v = fmaxf(acc[c][j] + bv, 0.f);
                int l = lb + j;
                if (part == 0)      g_k[(mm * 64 + cc) * 1024 + l] = v;
                else if (part == 2) g_q[(mm * 64 + cc) * 1024 + l] = v;
                else                g_vt[(mm * 1024 + l) * 64 + cc] = v;
            }
        }
    } else {
        const int h = r0 + pr;
#pragma unroll
        for (int c = 0; c < 4; c++) {
            int co = co0 + cg * 4 + c;
            float bv = bias[co];
#pragma unroll
            for (int j = 0; j < 8; j++) {
                int w = c0 + pc + j;
                int idx = ((b * 512 + co) * 96 + h) * 96 + w;
                out[idx] = resid[idx] + bv + acc[c][j];
            }
        }
    }
}

// ---------------------------------------------------------------------------
// Scores: T[m][j][i] = (1/8) * sum_c Q[m][c][j] * K[m][c][i]
// Tile 128j x 128i, K-dim 64 in two chunks of 32. 8x8 microtile.
// ---------------------------------------------------------------------------
__global__ __launch_bounds__(256) void att_gemm_kernel()
{
    const int m  = blockIdx.y;
    const int jt = blockIdx.x >> 3;
    const int it = blockIdx.x & 7;

    __shared__ float sQ[32][128];
    __shared__ float sK[32][128];

    const int tid = threadIdx.x;
    const int ty = tid >> 4, tx = tid & 15;

    float acc[8][8];
#pragma unroll
    for (int a = 0; a < 8; a++)
#pragma unroll
        for (int bq = 0; bq < 8; bq++) acc[a][bq] = 0.f;

    for (int cb = 0; cb < 64; cb += 32) {
#pragma unroll
        for (int t = 0; t < 4; t++) {
            int idx = tid + t * 256;              // 1024 float4 per matrix
            int r = idx >> 5, c4 = idx & 31;
            ((float4*)sQ[r])[c4] =
                *(const float4*)&g_q[(m * 64 + cb + r) * 1024 + jt * 128 + c4 * 4];
            ((float4*)sK[r])[c4] =
                *(const float4*)&g_k[(m * 64 + cb + r) * 1024 + it * 128 + c4 * 4];
        }
        __syncthreads();

#pragma unroll 8
        for (int cc = 0; cc < 32; cc++) {
            float a[8], bb[8];
            *(float4*)&a[0]  = *(float4*)&sQ[cc][ty * 8];
            *(float4*)&a[4]  = *(float4*)&sQ[cc][ty * 8 + 4];
            *(float4*)&bb[0] = *(float4*)&sK[cc][tx * 8];
            *(float4*)&bb[4] = *(float4*)&sK[cc][tx * 8 + 4];
#pragma unroll
            for (int jj = 0; jj < 8; jj++)
#pragma unroll
                for (int ii = 0; ii < 8; ii++)
                    acc[jj][ii] = fmaf(a[jj], bb[ii], acc[jj][ii]);
        }
        __syncthreads();
    }

#pragma unroll
    for (int jj = 0; jj < 8; jj++) {
        int j = jt * 128 + ty * 8 + jj;
        float* p = &g_att[(m * 1024 + j) * 1024 + it * 128 + tx * 8];
        float4 o0, o1;
        o0.x = acc[jj][0] * 0.125f; o0.y = acc[jj][1] * 0.125f;
        o0.z = acc[jj][2] * 0.125f; o0.w = acc[jj][3] * 0.125f;
        o1.x = acc[jj][4] * 0.125f; o1.y = acc[jj][5] * 0.125f;
        o1.z = acc[jj][6] * 0.125f; o1.w = acc[jj][7] * 0.125f;
        *(float4*)p       = o0;
        *(float4*)(p + 4) = o1;
    }
}

// ---------------------------------------------------------------------------
// Softmax over i (contiguous rows of g_att) + transpose into g_att2[i][j].
// One warp per j row; 32 warps/block cover 32 rows; smem 32x33 transpose.
// ---------------------------------------------------------------------------
__global__ __launch_bounds__(1024) void softmax_t_kernel()
{
    const int m  = blockIdx.y;
    const int j0 = blockIdx.x * 32;
    const int warp = threadIdx.x >> 5;
    const int lane = threadIdx.x & 31;

    const float* row = &g_att[((size_t)m * 1024 + j0 + warp) * 1024];
    float v[32];
#pragma unroll
    for (int t = 0; t < 32; t++) v[t] = row[t * 32 + lane];

    float mx = v[0];
#pragma unroll
    for (int t = 1; t < 32; t++) mx = fmaxf(mx, v[t]);
#pragma unroll
    for (int o = 16; o; o >>= 1) mx = fmaxf(mx, __shfl_xor_sync(0xffffffffu, mx, o));

    float s = 0.f;
#pragma unroll
    for (int t = 0; t < 32; t++) { v[t] = __expf(v[t] - mx); s += v[t]; }
#pragma unroll
    for (int o = 16; o; o >>= 1) s += __shfl_xor_sync(0xffffffffu, s, o);

    float inv = 1.0f / s;
#pragma unroll
    for (int t = 0; t < 32; t++) v[t] *= inv;

    __shared__ float sm[32][33];
    for (int t = 0; t < 32; t++) {
        __syncthreads();
        sm[lane][warp] = v[t];                     // p[j0+warp][i = t*32+lane]
        __syncthreads();
        g_att2[((size_t)m * 1024 + t * 32 + warp) * 1024 + j0 + lane] = sm[warp][lane];
    }
}

// ---------------------------------------------------------------------------
// o[m][c][j] = sum_i V[m][c][i] * P[m][i][j].  V in g_vt[m][i][c].
// Tile: all 64 c x 128 j, i streamed in chunks of 32. Thread: 8c x 4j.
// Epilogue scatters into spatial g_o (un-windowing fused).
// ---------------------------------------------------------------------------
__global__ __launch_bounds__(256) void o_gemm_kernel()
{
    const int m  = blockIdx.y;
    const int jt = blockIdx.x;

    __shared__ float sV[32][64];    // [i][c]
    __shared__ float sP[32][128];   // [i][j]

    const int tid = threadIdx.x;
    const int cgw = tid >> 5;       // warp id = c group (8 c each)
    const int jg  = tid & 31;       // 4 j each

    float acc[8][4];
#pragma unroll
    for (int c = 0; c < 8; c++)
#pragma unroll
        for (int j = 0; j < 4; j++) acc[c][j] = 0.f;

    for (int i0 = 0; i0 < 1024; i0 += 32) {
#pragma unroll
        for (int t = 0; t < 2; t++) {
            int idx = tid + t * 256;               // 512 float4
            int r = idx >> 4, c4 = idx & 15;
            ((float4*)sV[r])[c4] =
                *(const float4*)&g_vt[((size_t)m * 1024 + i0 + r) * 64 + c4 * 4];
        }
#pragma unroll
        for (int t = 0; t < 4; t++) {
            int idx = tid + t * 256;               // 1024 float4
            int r = idx >> 5, c4 = idx & 31;
            ((float4*)sP[r])[c4] =
                *(const float4*)&g_att2[((size_t)m * 1024 + i0 + r) * 1024 + jt * 128 + c4 * 4];
        }
        __syncthreads();

#pragma unroll 8
        for (int i = 0; i < 32; i++) {
            float a[8], bb[4];
            *(float4*)&a[0]  = *(float4*)&sV[i][cgw * 8];
            *(float4*)&a[4]  = *(float4*)&sV[i][cgw * 8 + 4];
            *(float4*)&bb[0] = *(float4*)&sP[i][jg * 4];
#pragma unroll
            for (int c = 0; c < 8; c++)
#pragma unroll
                for (int j = 0; j < 4; j++)
                    acc[c][j] = fmaf(a[c], bb[j], acc[c][j]);
        }
        __syncthreads();
    }

    const int n = m >> 2, hh = m & 3;
    const int b = n / 9, rem = n % 9;
    const int wh = rem / 3, ww = rem % 3;
#pragma unroll
    for (int c = 0; c < 8; c++) {
        int ch = hh * 64 + cgw * 8 + c;
#pragma unroll
        for (int jj = 0; jj < 4; jj++) {
            int j = jt * 128 + jg * 4 + jj;
            int si = j >> 5, sj = j & 31;
            int h = wh * 32 + si, w = ww * 32 + sj;
            g_o[((b * 256 + ch) * 96 + h) * 96 + w] = acc[c][jj];
        }
    }
}

// ---------------------------------------------------------------------------
extern "C" void kernel_launch(void* const* d_in, const int* in_sizes, int n_in,
                              void* d_out, int out_size)
{
    (void)in_sizes; (void)n_in; (void)out_size;
    const float* x  = (const float*)d_in[0];
    const float* W1 = (const float*)d_in[1];
    const float* b1 = (const float*)d_in[2];
    const float* W2 = (const float*)d_in[3];
    const float* b2 = (const float*)d_in[4];
    float* out = (float*)d_out;

    // conv1 + ReLU -> packed K/Q/V
    conv3x3_kernel<512, 0><<<dim3(72, 12, 2), 256>>>(x, W1, b1, nullptr, nullptr);
    // scores
    att_gemm_kernel<<<dim3(64, 72), 256>>>();
    // softmax over keys + transpose
    softmax_t_kernel<<<dim3(32, 72), 1024>>>();
    // PV -> spatial o
    o_gemm_kernel<<<dim3(8, 72), 256>>>();
    // conv2 + bias + residual -> out
    conv3x3_kernel<256, 1><<<dim3(72, 8, 2), 256>>>(nullptr, W2, b2, x, out);
}

// round 3
// speedup vs baseline: 2.4409x; 2.4409x over previous
#include <cuda_runtime.h>
#include <math.h>
#include <stdint.h>

// ===========================================================================
// LocalAttention on sm_100 (portable PTX only — no tcgen05 at this target):
//   conv3x3(512->768)+ReLU  -> tf32 mma.sync implicit GEMM, packs K/Q/V
//   windowed attention (72 (win,head), L=1024, d=64) -> fp32 SIMT
//   conv3x3(256->512)+residual -> tf32 mma.sync implicit GEMM
// ===========================================================================

// ------------------------------- scratch ----------------------------------
__device__ float g_k  [72 * 64 * 1024];
__device__ float g_q  [72 * 64 * 1024];
__device__ float g_vt [72 * 1024 * 64];
__device__ float g_att [72 * 1024 * 1024];
__device__ float g_att2[72 * 1024 * 1024];
__device__ float g_o  [2 * 256 * 96 * 96];
__device__ float g_xcl[2 * 98 * 98 * 512];   // padded channels-last input (tf32-rounded)
__device__ float g_ocl[2 * 98 * 98 * 256];   // padded channels-last attention out
__device__ float g_w1p[9 * 768 * 512];       // W1 repacked [s][co][ci], tf32-rounded
__device__ float g_w2p[9 * 512 * 256];       // W2 repacked [s][co][ci]

// ------------------------------ helpers -----------------------------------
__device__ __forceinline__ uint32_t smem_u32(const void* p) {
    uint32_t a;
    asm("{ .reg .u64 t; cvta.to.shared.u64 t, %1; cvt.u32.u64 %0, t; }" : "=r"(a) : "l"(p));
    return a;
}
__device__ __forceinline__ float rtf32(float v) {
    uint32_t o;
    asm("cvt.rna.tf32.f32 %0, %1;" : "=r"(o) : "f"(v));
    return __uint_as_float(o);
}

#define CP_ASYNC16(sm, gm) \
    asm volatile("cp.async.cg.shared.global [%0], [%1], 16;" :: "r"(sm), "l"(gm))
#define CP_COMMIT() asm volatile("cp.async.commit_group;" ::: "memory")
#define CP_WAIT1()  asm volatile("cp.async.wait_group 1;" ::: "memory")
#define CP_WAIT0()  asm volatile("cp.async.wait_group 0;" ::: "memory")

#define MMA_TF32(c0,c1,c2,c3, a0,a1,a2,a3, b0,b1) \
    asm volatile("mma.sync.aligned.m16n8k8.row.col.f32.tf32.tf32.f32 " \
        "{%0,%1,%2,%3}, {%4,%5,%6,%7}, {%8,%9}, {%0,%1,%2,%3};" \
        : "+f"(c0), "+f"(c1), "+f"(c2), "+f"(c3) \
        : "r"(a0), "r"(a1), "r"(a2), "r"(a3), "r"(b0), "r"(b1))

// ===========================================================================
// Pack kernels
// ===========================================================================
template <int C>
__global__ void fill_border_kernel() {
    float* out = (C == 512) ? g_xcl : g_ocl;
    int idx = blockIdx.x * 256 + threadIdx.x;
    const int c4n = C / 4;
    const int total = 2 * 388 * c4n;
    if (idx >= total) return;
    int c4 = idx % c4n;
    int cell = (idx / c4n) % 388;
    int b = idx / (388 * c4n);
    int h, w;
    if (cell < 98)        { h = 0;  w = cell; }
    else if (cell < 196)  { h = 97; w = cell - 98; }
    else if (cell < 292)  { h = cell - 196 + 1; w = 0; }
    else                  { h = cell - 292 + 1; w = 97; }
    float4 z = make_float4(0.f, 0.f, 0.f, 0.f);
    ((float4*)&out[(((size_t)b * 98 + h) * 98 + w) * C])[c4] = z;
}

// NCHW -> padded channels-last with tf32 rounding. SRC=0: param ptr, SRC=1: g_o
template <int C, int SRC>
__global__ __launch_bounds__(256) void pack_cl_kernel(const float* __restrict__ in_p) {
    const float* in = (SRC == 0) ? in_p : g_o;
    float* out = (C == 512) ? g_xcl : g_ocl;
    __shared__ float s[32][97];
    const int h = blockIdx.x, cig = blockIdx.y, b = blockIdx.z;
    const int tid = threadIdx.x;
    for (int e = tid; e < 32 * 96; e += 256) {
        int ci = e / 96, w = e % 96;
        s[ci][w] = in[(((size_t)b * C + cig * 32 + ci) * 96 + h) * 96 + w];
    }
    __syncthreads();
    for (int e = tid; e < 96 * 32; e += 256) {
        int w = e >> 5, ci = e & 31;
        out[(((size_t)b * 98 + h + 1) * 98 + (w + 1)) * C + cig * 32 + ci] = rtf32(s[ci][w]);
    }
}

// W[co][ci][3][3] -> Wp[s][co][ci] with tf32 rounding
template <int CO, int CI, int WHICH>
__global__ void repack_w_kernel(const float* __restrict__ W) {
    float* Wp = (WHICH == 0) ? g_w1p : g_w2p;
    int idx = blockIdx.x * 256 + threadIdx.x;
    const int total = 9 * CO * CI;
    if (idx >= total) return;
    int s = idx / (CO * CI);
    int rem = idx % (CO * CI);
    int co = rem / CI, ci = rem % CI;
    Wp[idx] = rtf32(W[((size_t)co * CI + ci) * 9 + s]);
}

// ===========================================================================
// tf32 mma.sync implicit-GEMM conv3x3.
// CTA: D[128 co x 128 px]; px tile = 4 rows x 32 cols. 8 warps (2M x 4N),
// warp tile 64x32 via m16n8k8 (4 m-frags x 4 n-frags).
// smem: A[128 co][36] and B[128 px][36] per buffer, K-chunk = 32, double buf.
// MODE 0: bias+ReLU -> packed K/Q/V.  MODE 1: bias+residual -> out.
// ===========================================================================
template <int CIN, int COUT, int MODE>
__global__ void __launch_bounds__(256, 2)
conv_mma_kernel(const float* __restrict__ bias,
                const float* __restrict__ resid,
                float* __restrict__ out)
{
    constexpr int NIT = 9 * CIN / 32;
    constexpr int ABUF = 128 * 36;            // floats per A buffer
    constexpr int BUF  = 2 * ABUF;            // floats per (A+B) buffer

    const float* __restrict__ Wp  = (MODE == 0) ? g_w1p : g_w2p;
    const float* __restrict__ xcl = (MODE == 0) ? g_xcl : g_ocl;

    extern __shared__ float smf[];
    const uint32_t sb = smem_u32(smf);

    const int tid  = threadIdx.x;
    const int wid  = tid >> 5;
    const int lane = tid & 31;
    const int g = lane >> 2;      // 0..7
    const int t = lane & 3;       // 0..3
    const int wm = wid >> 2;      // 0..1 : M 64-half
    const int wn = wid & 3;       // 0..3 : N 32-quarter

    const int pt = blockIdx.x;          // 144 tiles = b(2) x 24 rowbands x 3 colbands
    const int b  = pt / 72;
    const int r  = pt % 72;
    const int h0 = (r / 3) * 4;
    const int w0 = (r % 3) * 32;
    const int co0 = blockIdx.y * 128;

    const int arow  = tid >> 1;          // row handled by this thread (A and B)
    const int ahalf = (tid & 1) * 64;    // byte half of the 128B row

    auto load_stage = [&](int it, int buf) {
        const int s   = it / (CIN / 32);
        const int ci0 = (it % (CIN / 32)) * 32;
        const int kh = s / 3, kw = s % 3;
        const uint32_t abase = sb + (buf * BUF + arow * 36) * 4 + ahalf;
        const uint32_t bbase = abase + ABUF * 4;
        const char* ga = (const char*)(Wp + ((size_t)s * COUT + co0 + arow) * CIN + ci0) + ahalf;
#pragma unroll
        for (int i = 0; i < 4; i++) CP_ASYNC16(abase + i * 16, ga + i * 16);
        const int pr = arow >> 5, pc = arow & 31;
        const char* gb = (const char*)
            (xcl + (((size_t)(b * 98 + h0 + pr + kh)) * 98 + (w0 + pc + kw)) * CIN + ci0) + ahalf;
#pragma unroll
        for (int i = 0; i < 4; i++) CP_ASYNC16(bbase + i * 16, gb + i * 16);
        CP_COMMIT();
    };

    float acc[4][4][4];
#pragma unroll
    for (int mf = 0; mf < 4; mf++)
#pragma unroll
        for (int nf = 0; nf < 4; nf++)
#pragma unroll
            for (int e = 0; e < 4; e++) acc[mf][nf][e] = 0.f;

    load_stage(0, 0);

    for (int it = 0; it < NIT; ++it) {
        const int buf = it & 1;
        if (it + 1 < NIT) { load_stage(it + 1, buf ^ 1); CP_WAIT1(); }
        else              { CP_WAIT0(); }
        __syncthreads();

        const float* Sa = smf + buf * BUF;
        const float* Sb = Sa + ABUF;
#pragma unroll
        for (int k0 = 0; k0 < 32; k0 += 8) {
            uint32_t bf[4][2];
#pragma unroll
            for (int nf = 0; nf < 4; nf++) {
                int n = wn * 32 + nf * 8 + g;
                bf[nf][0] = __float_as_uint(Sb[n * 36 + k0 + t]);
                bf[nf][1] = __float_as_uint(Sb[n * 36 + k0 + t + 4]);
            }
#pragma unroll
            for (int mf = 0; mf < 4; mf++) {
                int m = wm * 64 + mf * 16 + g;
                uint32_t a0 = __float_as_uint(Sa[m * 36 + k0 + t]);
                uint32_t a1 = __float_as_uint(Sa[(m + 8) * 36 + k0 + t]);
                uint32_t a2 = __float_as_uint(Sa[m * 36 + k0 + t + 4]);
                uint32_t a3 = __float_as_uint(Sa[(m + 8) * 36 + k0 + t + 4]);
#pragma unroll
                for (int nf = 0; nf < 4; nf++)
                    MMA_TF32(acc[mf][nf][0], acc[mf][nf][1], acc[mf][nf][2], acc[mf][nf][3],
                             a0, a1, a2, a3, bf[nf][0], bf[nf][1]);
            }
        }
        __syncthreads();
    }

    // ----------------------------- epilogue -------------------------------
#pragma unroll
    for (int mf = 0; mf < 4; mf++) {
#pragma unroll
        for (int half8 = 0; half8 < 2; half8++) {
            const int co_g = co0 + wm * 64 + mf * 16 + g + half8 * 8;
            const float bv = __ldg(&bias[co_g]);
            if (MODE == 0) {
                const int part = co_g >> 8;          // 0=K 1=V 2=Q
                const int hh   = (co_g >> 6) & 3;
                const int cc   = co_g & 63;
                const int mm   = ((b * 9 + (h0 >> 5) * 3 + (w0 >> 5)) << 2) + hh;
#pragma unroll
                for (int nf = 0; nf < 4; nf++) {
                    const int px0 = wn * 32 + nf * 8 + 2 * t;
                    float v0 = fmaxf(acc[mf][nf][half8 * 2 + 0] + bv, 0.f);
                    float v1 = fmaxf(acc[mf][nf][half8 * 2 + 1] + bv, 0.f);
                    const int l0 = ((h0 & 31) + (px0 >> 5)) * 32 + (px0 & 31);
                    if (part == 1) {
                        float* dv = g_vt + ((size_t)mm * 1024 + l0) * 64 + cc;
                        dv[0]  = v0;
                        dv[64] = v1;
                    } else {
                        float* dst = (part ? g_q : g_k) + ((size_t)(mm * 64 + cc)) * 1024 + l0;
                        *(float2*)dst = make_float2(v0, v1);
                    }
                }
            } else {
#pragma unroll
                for (int nf = 0; nf < 4; nf++) {
                    const int px0 = wn * 32 + nf * 8 + 2 * t;
                    const int h = h0 + (px0 >> 5), w = w0 + (px0 & 31);
                    const size_t idx = (((size_t)(b * 512 + co_g) * 96) + h) * 96 + w;
                    float2 rv = *(const float2*)(resid + idx);
                    float2 v;
                    v.x = rv.x + bv + acc[mf][nf][half8 * 2 + 0];
                    v.y = rv.y + bv + acc[mf][nf][half8 * 2 + 1];
                    *(float2*)(out + idx) = v;
                }
            }
        }
    }
}

// ===========================================================================
// Attention (fp32 SIMT)
// ===========================================================================
__global__ __launch_bounds__(256) void att_gemm_kernel()
{
    const int m  = blockIdx.y;
    const int jt = blockIdx.x >> 3;
    const int it = blockIdx.x & 7;

    __shared__ float sQ[32][128];
    __shared__ float sK[32][128];

    const int tid = threadIdx.x;
    const int ty = tid >> 4, tx = tid & 15;

    float acc[8][8];
#pragma unroll
    for (int a = 0; a < 8; a++)
#pragma unroll
        for (int bq = 0; bq < 8; bq++) acc[a][bq] = 0.f;

    for (int cb = 0; cb < 64; cb += 32) {
#pragma unroll
        for (int tt = 0; tt < 4; tt++) {
            int idx = tid + tt * 256;
            int rr = idx >> 5, c4 = idx & 31;
            ((float4*)sQ[rr])[c4] =
                *(const float4*)&g_q[(m * 64 + cb + rr) * 1024 + jt * 128 + c4 * 4];
            ((float4*)sK[rr])[c4] =
                *(const float4*)&g_k[(m * 64 + cb + rr) * 1024 + it * 128 + c4 * 4];
        }
        __syncthreads();

#pragma unroll 8
        for (int cc = 0; cc < 32; cc++) {
            float a[8], bb[8];
            *(float4*)&a[0]  = *(float4*)&sQ[cc][ty * 8];
            *(float4*)&a[4]  = *(float4*)&sQ[cc][ty * 8 + 4];
            *(float4*)&bb[0] = *(float4*)&sK[cc][tx * 8];
            *(float4*)&bb[4] = *(float4*)&sK[cc][tx * 8 + 4];
#pragma unroll
            for (int jj = 0; jj < 8; jj++)
#pragma unroll
                for (int ii = 0; ii < 8; ii++)
                    acc[jj][ii] = fmaf(a[jj], bb[ii], acc[jj][ii]);
        }
        __syncthreads();
    }

#pragma unroll
    for (int jj = 0; jj < 8; jj++) {
        int j = jt * 128 + ty * 8 + jj;
        float* p = &g_att[((size_t)m * 1024 + j) * 1024 + it * 128 + tx * 8];
        float4 o0, o1;
        o0.x = acc[jj][0] * 0.125f; o0.y = acc[jj][1] * 0.125f;
        o0.z = acc[jj][2] * 0.125f; o0.w = acc[jj][3] * 0.125f;
        o1.x = acc[jj][4] * 0.125f; o1.y = acc[jj][5] * 0.125f;
        o1.z = acc[jj][6] * 0.125f; o1.w = acc[jj][7] * 0.125f;
        *(float4*)p       = o0;
        *(float4*)(p + 4) = o1;
    }
}

__global__ __launch_bounds__(1024) void softmax_t_kernel()
{
    const int m  = blockIdx.y;
    const int j0 = blockIdx.x * 32;
    const int warp = threadIdx.x >> 5;
    const int lane = threadIdx.x & 31;

    const float* row = &g_att[((size_t)m * 1024 + j0 + warp) * 1024];
    float v[32];
#pragma unroll
    for (int t = 0; t < 32; t++) v[t] = row[t * 32 + lane];

    float mx = v[0];
#pragma unroll
    for (int t = 1; t < 32; t++) mx = fmaxf(mx, v[t]);
#pragma unroll
    for (int o = 16; o; o >>= 1) mx = fmaxf(mx, __shfl_xor_sync(0xffffffffu, mx, o));

    float s = 0.f;
#pragma unroll
    for (int t = 0; t < 32; t++) { v[t] = __expf(v[t] - mx); s += v[t]; }
#pragma unroll
    for (int o = 16; o; o >>= 1) s += __shfl_xor_sync(0xffffffffu, s, o);

    float inv = 1.0f / s;
#pragma unroll
    for (int t = 0; t < 32; t++) v[t] *= inv;

    __shared__ float sm[32][33];
    for (int t = 0; t < 32; t++) {
        __syncthreads();
        sm[lane][warp] = v[t];
        __syncthreads();
        g_att2[((size_t)m * 1024 + t * 32 + warp) * 1024 + j0 + lane] = sm[warp][lane];
    }
}

__global__ __launch_bounds__(256) void o_gemm_kernel()
{
    const int m  = blockIdx.y;
    const int jt = blockIdx.x;

    __shared__ float sV[32][64];
    __shared__ float sP[32][128];

    const int tid = threadIdx.x;
    const int cgw = tid >> 5;
    const int jg  = tid & 31;

    float acc[8][4];
#pragma unroll
    for (int c = 0; c < 8; c++)
#pragma unroll
        for (int j = 0; j < 4; j++) acc[c][j] = 0.f;

    for (int i0 = 0; i0 < 1024; i0 += 32) {
#pragma unroll
        for (int t = 0; t < 2; t++) {
            int idx = tid + t * 256;
            int r = idx >> 4, c4 = idx & 15;
            ((float4*)sV[r])[c4] =
                *(const float4*)&g_vt[((size_t)m * 1024 + i0 + r) * 64 + c4 * 4];
        }
#pragma unroll
        for (int t = 0; t < 4; t++) {
            int idx = tid + t * 256;
            int r = idx >> 5, c4 = idx & 31;
            ((float4*)sP[r])[c4] =
                *(const float4*)&g_att2[((size_t)m * 1024 + i0 + r) * 1024 + jt * 128 + c4 * 4];
        }
        __syncthreads();

#pragma unroll 8
        for (int i = 0; i < 32; i++) {
            float a[8], bb[4];
            *(float4*)&a[0]  = *(float4*)&sV[i][cgw * 8];
            *(float4*)&a[4]  = *(float4*)&sV[i][cgw * 8 + 4];
            *(float4*)&bb[0] = *(float4*)&sP[i][jg * 4];
#pragma unroll
            for (int c = 0; c < 8; c++)
#pragma unroll
                for (int j = 0; j < 4; j++)
                    acc[c][j] = fmaf(a[c], bb[j], acc[c][j]);
        }
        __syncthreads();
    }

    const int n = m >> 2, hh = m & 3;
    const int b = n / 9, rem = n % 9;
    const int wh = rem / 3, ww = rem % 3;
#pragma unroll
    for (int c = 0; c < 8; c++) {
        int ch = hh * 64 + cgw * 8 + c;
#pragma unroll
        for (int jj = 0; jj < 4; jj++) {
            int j = jt * 128 + jg * 4 + jj;
            int si = j >> 5, sj = j & 31;
            int h = wh * 32 + si, w = ww * 32 + sj;
            g_o[(((size_t)b * 256 + ch) * 96 + h) * 96 + w] = acc[c][jj];
        }
    }
}

// ===========================================================================
extern "C" void kernel_launch(void* const* d_in, const int* in_sizes, int n_in,
                              void* d_out, int out_size)
{
    (void)in_sizes; (void)n_in; (void)out_size;
    const float* x  = (const float*)d_in[0];
    const float* W1 = (const float*)d_in[1];
    const float* b1 = (const float*)d_in[2];
    const float* W2 = (const float*)d_in[3];
    const float* b2 = (const float*)d_in[4];
    float* out = (float*)d_out;

    const int SMEM_BYTES = 2 * 2 * 128 * 36 * 4;   // 73728
    cudaFuncSetAttribute(conv_mma_kernel<512, 768, 0>,
                         cudaFuncAttributeMaxDynamicSharedMemorySize, SMEM_BYTES);
    cudaFuncSetAttribute(conv_mma_kernel<256, 512, 1>,
                         cudaFuncAttributeMaxDynamicSharedMemorySize, SMEM_BYTES);

    // pack inputs / weights (tf32-rounded)
    fill_border_kernel<512><<<(2 * 388 * 128 + 255) / 256, 256>>>();
    fill_border_kernel<256><<<(2 * 388 * 64 + 255) / 256, 256>>>();
    pack_cl_kernel<512, 0><<<dim3(96, 16, 2), 256>>>(x);
    repack_w_kernel<768, 512, 0><<<(9 * 768 * 512 + 255) / 256, 256>>>(W1);
    repack_w_kernel<512, 256, 1><<<(9 * 512 * 256 + 255) / 256, 256>>>(W2);

    // conv1 + ReLU -> packed K/Q/V (tf32 mma)
    conv_mma_kernel<512, 768, 0><<<dim3(144, 6), 256, SMEM_BYTES>>>(b1, nullptr, nullptr);

    // attention
    att_gemm_kernel<<<dim3(64, 72), 256>>>();
    softmax_t_kernel<<<dim3(32, 72), 1024>>>();
    o_gemm_kernel<<<dim3(8, 72), 256>>>();

    // conv2 + residual (tf32 mma)
    pack_cl_kernel<256, 1><<<dim3(96, 8, 2), 256>>>(nullptr);
    conv_mma_kernel<256, 512, 1><<<dim3(144, 4), 256, SMEM_BYTES>>>(b2, x, out);
}

// round 4
// speedup vs baseline: 3.0611x; 1.2541x over previous
#include <cuda_runtime.h>
#include <math.h>
#include <stdint.h>

// ===========================================================================
// LocalAttention on sm_100 (portable PTX, tensor pipe via mma.sync tf32):
//   conv3x3(512->768)+ReLU  -> tf32 mma implicit GEMM, packs Q/K [m][l][c], V [m][c][l]
//   fused flash-style windowed attention -> writes conv2 input (channels-last)
//   conv3x3(256->512)+residual -> tf32 mma implicit GEMM
// ===========================================================================

// ------------------------------- scratch ----------------------------------
__device__ float g_kt [72 * 1024 * 64];      // K: [m][i][c]   (tf32-rounded)
__device__ float g_qt [72 * 1024 * 64];      // Q: [m][j][c]
__device__ float g_v  [72 * 64 * 1024];      // V: [m][c][i]
__device__ float g_xcl[2 * 98 * 98 * 512];   // padded channels-last input
__device__ float g_ocl[2 * 98 * 98 * 256];   // padded channels-last attn output
__device__ float g_w1p[9 * 768 * 512];       // W1 [s][co][ci], tf32-rounded
__device__ float g_w2p[9 * 512 * 256];       // W2 [s][co][ci]

// ------------------------------ helpers -----------------------------------
__device__ __forceinline__ uint32_t smem_u32(const void* p) {
    uint32_t a;
    asm("{ .reg .u64 t; cvta.to.shared.u64 t, %1; cvt.u32.u64 %0, t; }" : "=r"(a) : "l"(p));
    return a;
}
__device__ __forceinline__ float rtf32(float v) {
    uint32_t o;
    asm("cvt.rna.tf32.f32 %0, %1;" : "=r"(o) : "f"(v));
    return __uint_as_float(o);
}

#define CP_ASYNC16(sm, gm) \
    asm volatile("cp.async.cg.shared.global [%0], [%1], 16;" :: "r"(sm), "l"(gm))
#define CP_COMMIT() asm volatile("cp.async.commit_group;" ::: "memory")
#define CP_WAIT1()  asm volatile("cp.async.wait_group 1;" ::: "memory")
#define CP_WAIT0()  asm volatile("cp.async.wait_group 0;" ::: "memory")

#define MMA_TF32(c0,c1,c2,c3, a0,a1,a2,a3, b0,b1) \
    asm volatile("mma.sync.aligned.m16n8k8.row.col.f32.tf32.tf32.f32 " \
        "{%0,%1,%2,%3}, {%4,%5,%6,%7}, {%8,%9}, {%0,%1,%2,%3};" \
        : "+f"(c0), "+f"(c1), "+f"(c2), "+f"(c3) \
        : "r"(a0), "r"(a1), "r"(a2), "r"(a3), "r"(b0), "r"(b1))

// ===========================================================================
// Pack kernels
// ===========================================================================
template <int C>
__global__ void fill_border_kernel() {
    float* out = (C == 512) ? g_xcl : g_ocl;
    int idx = blockIdx.x * 256 + threadIdx.x;
    const int c4n = C / 4;
    const int total = 2 * 388 * c4n;
    if (idx >= total) return;
    int c4 = idx % c4n;
    int cell = (idx / c4n) % 388;
    int b = idx / (388 * c4n);
    int h, w;
    if (cell < 98)        { h = 0;  w = cell; }
    else if (cell < 196)  { h = 97; w = cell - 98; }
    else if (cell < 292)  { h = cell - 196 + 1; w = 0; }
    else                  { h = cell - 292 + 1; w = 97; }
    float4 z = make_float4(0.f, 0.f, 0.f, 0.f);
    ((float4*)&out[(((size_t)b * 98 + h) * 98 + w) * C])[c4] = z;
}

__global__ __launch_bounds__(256) void pack_cl_kernel(const float* __restrict__ in) {
    __shared__ float s[32][97];
    const int h = blockIdx.x, cig = blockIdx.y, b = blockIdx.z;
    const int tid = threadIdx.x;
    for (int e = tid; e < 32 * 96; e += 256) {
        int ci = e / 96, w = e % 96;
        s[ci][w] = in[(((size_t)b * 512 + cig * 32 + ci) * 96 + h) * 96 + w];
    }
    __syncthreads();
    for (int e = tid; e < 96 * 32; e += 256) {
        int w = e >> 5, ci = e & 31;
        g_xcl[(((size_t)b * 98 + h + 1) * 98 + (w + 1)) * 512 + cig * 32 + ci] = rtf32(s[ci][w]);
    }
}

template <int CO, int CI, int WHICH>
__global__ void repack_w_kernel(const float* __restrict__ W) {
    float* Wp = (WHICH == 0) ? g_w1p : g_w2p;
    int idx = blockIdx.x * 256 + threadIdx.x;
    const int total = 9 * CO * CI;
    if (idx >= total) return;
    int s = idx / (CO * CI);
    int rem = idx % (CO * CI);
    int co = rem / CI, ci = rem % CI;
    Wp[idx] = rtf32(W[((size_t)co * CI + ci) * 9 + s]);
}

// ===========================================================================
// tf32 mma.sync implicit-GEMM conv3x3 (CTA 128co x 128px, 8 warps 64x32).
// MODE 0: bias+ReLU -> tf32-rounded Q/K [m][l][c] and V [m][c][l].
// MODE 1: bias+residual -> out (fp32 exact epilogue).
// ===========================================================================
template <int CIN, int COUT, int MODE>
__global__ void __launch_bounds__(256, 2)
conv_mma_kernel(const float* __restrict__ bias,
                const float* __restrict__ resid,
                float* __restrict__ out)
{
    constexpr int NIT = 9 * CIN / 32;
    constexpr int ABUF = 128 * 36;
    constexpr int BUF  = 2 * ABUF;

    const float* __restrict__ Wp  = (MODE == 0) ? g_w1p : g_w2p;
    const float* __restrict__ xcl = (MODE == 0) ? g_xcl : g_ocl;
    const int XC = (MODE == 0) ? 512 : 256;

    extern __shared__ float smf[];
    const uint32_t sb = smem_u32(smf);

    const int tid  = threadIdx.x;
    const int wid  = tid >> 5;
    const int lane = tid & 31;
    const int g = lane >> 2;
    const int t = lane & 3;
    const int wm = wid >> 2;
    const int wn = wid & 3;

    const int pt = blockIdx.x;
    const int b  = pt / 72;
    const int r  = pt % 72;
    const int h0 = (r / 3) * 4;
    const int w0 = (r % 3) * 32;
    const int co0 = blockIdx.y * 128;

    const int arow  = tid >> 1;
    const int ahalf = (tid & 1) * 64;

    auto load_stage = [&](int it, int buf) {
        const int s   = it / (CIN / 32);
        const int ci0 = (it % (CIN / 32)) * 32;
        const int kh = s / 3, kw = s % 3;
        const uint32_t abase = sb + (buf * BUF + arow * 36) * 4 + ahalf;
        const uint32_t bbase = abase + ABUF * 4;
        const char* ga = (const char*)(Wp + ((size_t)s * COUT + co0 + arow) * CIN + ci0) + ahalf;
#pragma unroll
        for (int i = 0; i < 4; i++) CP_ASYNC16(abase + i * 16, ga + i * 16);
        const int pr = arow >> 5, pc = arow & 31;
        const char* gb = (const char*)
            (xcl + (((size_t)(b * 98 + h0 + pr + kh)) * 98 + (w0 + pc + kw)) * XC + ci0) + ahalf;
#pragma unroll
        for (int i = 0; i < 4; i++) CP_ASYNC16(bbase + i * 16, gb + i * 16);
        CP_COMMIT();
    };

    float acc[4][4][4];
#pragma unroll
    for (int mf = 0; mf < 4; mf++)
#pragma unroll
        for (int nf = 0; nf < 4; nf++)
#pragma unroll
            for (int e = 0; e < 4; e++) acc[mf][nf][e] = 0.f;

    load_stage(0, 0);

    for (int it = 0; it < NIT; ++it) {
        const int buf = it & 1;
        if (it + 1 < NIT) { load_stage(it + 1, buf ^ 1); CP_WAIT1(); }
        else              { CP_WAIT0(); }
        __syncthreads();

        const float* Sa = smf + buf * BUF;
        const float* Sb = Sa + ABUF;
#pragma unroll
        for (int k0 = 0; k0 < 32; k0 += 8) {
            uint32_t bf[4][2];
#pragma unroll
            for (int nf = 0; nf < 4; nf++) {
                int n = wn * 32 + nf * 8 + g;
                bf[nf][0] = __float_as_uint(Sb[n * 36 + k0 + t]);
                bf[nf][1] = __float_as_uint(Sb[n * 36 + k0 + t + 4]);
            }
#pragma unroll
            for (int mf = 0; mf < 4; mf++) {
                int m = wm * 64 + mf * 16 + g;
                uint32_t a0 = __float_as_uint(Sa[m * 36 + k0 + t]);
                uint32_t a1 = __float_as_uint(Sa[(m + 8) * 36 + k0 + t]);
                uint32_t a2 = __float_as_uint(Sa[m * 36 + k0 + t + 4]);
                uint32_t a3 = __float_as_uint(Sa[(m + 8) * 36 + k0 + t + 4]);
#pragma unroll
                for (int nf = 0; nf < 4; nf++)
                    MMA_TF32(acc[mf][nf][0], acc[mf][nf][1], acc[mf][nf][2], acc[mf][nf][3],
                             a0, a1, a2, a3, bf[nf][0], bf[nf][1]);
            }
        }
        __syncthreads();
    }

    // ----------------------------- epilogue -------------------------------
#pragma unroll
    for (int mf = 0; mf < 4; mf++) {
#pragma unroll
        for (int half8 = 0; half8 < 2; half8++) {
            const int co_g = co0 + wm * 64 + mf * 16 + g + half8 * 8;
            const float bv = __ldg(&bias[co_g]);
            if (MODE == 0) {
                const int part = co_g >> 8;          // 0=K 1=V 2=Q
                const int hh   = (co_g >> 6) & 3;
                const int cc   = co_g & 63;
                const int mm   = ((b * 9 + (h0 >> 5) * 3 + (w0 >> 5)) << 2) + hh;
#pragma unroll
                for (int nf = 0; nf < 4; nf++) {
                    const int px0 = wn * 32 + nf * 8 + 2 * t;
                    float v0 = rtf32(fmaxf(acc[mf][nf][half8 * 2 + 0] + bv, 0.f));
                    float v1 = rtf32(fmaxf(acc[mf][nf][half8 * 2 + 1] + bv, 0.f));
                    const int l0 = ((h0 & 31) + (px0 >> 5)) * 32 + (px0 & 31);
                    if (part == 1) {
                        float* dst = g_v + ((size_t)(mm * 64 + cc)) * 1024 + l0;
                        *(float2*)dst = make_float2(v0, v1);
                    } else {
                        float* dq = (part ? g_qt : g_kt) + ((size_t)mm * 1024 + l0) * 64 + cc;
                        dq[0]  = v0;
                        dq[64] = v1;
                    }
                }
            } else {
#pragma unroll
                for (int nf = 0; nf < 4; nf++) {
                    const int px0 = wn * 32 + nf * 8 + 2 * t;
                    const int h = h0 + (px0 >> 5), w = w0 + (px0 & 31);
                    const size_t idx = (((size_t)(b * 512 + co_g) * 96) + h) * 96 + w;
                    float2 rv = *(const float2*)(resid + idx);
                    float2 v;
                    v.x = rv.x + bv + acc[mf][nf][half8 * 2 + 0];
                    v.y = rv.y + bv + acc[mf][nf][half8 * 2 + 1];
                    *(float2*)(out + idx) = v;
                }
            }
        }
    }
}

// ===========================================================================
// Fused flash-style attention. CTA = (m, 128-j tile). 256 threads, 8 warps.
//   QK: warp = 16 j x 128 i  (softmax rows stay in one warp quad)
//   PV: warp = 32 c x 32 j
// Epilogue writes g_ocl (padded channels-last, tf32-rounded).
// ===========================================================================
__global__ void __launch_bounds__(256, 1) fused_attn_kernel()
{
    constexpr int QS = 68, KS = 68, VS = 132, PS = 132;
    extern __shared__ float sm[];
    float* sQ = sm;                       // [128][68]
    float* sK = sQ + 128 * QS;            // [128][68]
    float* sV = sK + 128 * KS;            // [64][132]
    float* sP = sV + 64 * VS;             // [128][132]
    float* sScale = sP + 128 * PS;        // [128]

    const int m  = blockIdx.y;
    const int jt = blockIdx.x;            // 0..7
    const int tid = threadIdx.x, wid = tid >> 5, lane = tid & 31;
    const int g = lane >> 2, t = lane & 3;
    const int wc = wid >> 2;              // PV c-half (0..1)
    const int wj = wid & 3;               // PV j-quarter (0..3)

    // ---- load Q tile [128 j][64 c] ----
    {
        const uint32_t sqb = smem_u32(sQ);
        const char* Qg = (const char*)(g_qt + ((size_t)m * 1024 + jt * 128) * 64);
        for (int e = tid; e < 2048; e += 256) {
            int r = e >> 4, c = e & 15;
            CP_ASYNC16(sqb + (r * QS + c * 4) * 4, Qg + (r * 64 + c * 4) * 4);
        }
    }

    float accO[2][4][4];
#pragma unroll
    for (int mf = 0; mf < 2; mf++)
#pragma unroll
        for (int nf = 0; nf < 4; nf++)
#pragma unroll
            for (int e = 0; e < 4; e++) accO[mf][nf][e] = 0.f;

    float m_run[2] = {-1e30f, -1e30f};
    float l_t[2]   = {0.f, 0.f};

    const uint32_t skb = smem_u32(sK), svb = smem_u32(sV);

    for (int ch = 0; ch < 8; ch++) {
        const int i0 = ch * 128;
        // ---- load K chunk [128 i][64 c], V chunk [64 c][128 i] ----
        const char* Kg = (const char*)(g_kt + ((size_t)m * 1024 + i0) * 64);
        const char* Vg = (const char*)(g_v + (size_t)m * 64 * 1024 + i0);
        for (int e = tid; e < 2048; e += 256) {
            int r = e >> 4, c = e & 15;
            CP_ASYNC16(skb + (r * KS + c * 4) * 4, Kg + (r * 64 + c * 4) * 4);
        }
        for (int e = tid; e < 2048; e += 256) {
            int r = e >> 5, c = e & 31;
            CP_ASYNC16(svb + (r * VS + c * 4) * 4, Vg + (r * 1024 + c * 4) * 4);
        }
        CP_COMMIT();
        CP_WAIT0();
        __syncthreads();

        // ---- QK: S[16 j][128 i] per warp ----
        float accS[16][4];
#pragma unroll
        for (int nf = 0; nf < 16; nf++)
#pragma unroll
            for (int e = 0; e < 4; e++) accS[nf][e] = 0.f;

        const int jr = wid * 16 + g;      // row for c0/c1; +8 for c2/c3
#pragma unroll
        for (int k0 = 0; k0 < 64; k0 += 8) {
            uint32_t a0 = __float_as_uint(sQ[jr * QS + k0 + t]);
            uint32_t a1 = __float_as_uint(sQ[(jr + 8) * QS + k0 + t]);
            uint32_t a2 = __float_as_uint(sQ[jr * QS + k0 + t + 4]);
            uint32_t a3 = __float_as_uint(sQ[(jr + 8) * QS + k0 + t + 4]);
#pragma unroll
            for (int nf = 0; nf < 16; nf++) {
                int n = nf * 8 + g;
                uint32_t b0 = __float_as_uint(sK[n * KS + k0 + t]);
                uint32_t b1 = __float_as_uint(sK[n * KS + k0 + t + 4]);
                MMA_TF32(accS[nf][0], accS[nf][1], accS[nf][2], accS[nf][3],
                         a0, a1, a2, a3, b0, b1);
            }
        }

        // ---- online softmax over i (cols), rows jr / jr+8 ----
        float cmax[2] = {-1e30f, -1e30f};
#pragma unroll
        for (int nf = 0; nf < 16; nf++) {
#pragma unroll
            for (int e = 0; e < 4; e++) accS[nf][e] *= 0.125f;
            cmax[0] = fmaxf(cmax[0], fmaxf(accS[nf][0], accS[nf][1]));
            cmax[1] = fmaxf(cmax[1], fmaxf(accS[nf][2], accS[nf][3]));
        }
#pragma unroll
        for (int o = 1; o <= 2; o <<= 1) {
            cmax[0] = fmaxf(cmax[0], __shfl_xor_sync(0xffffffffu, cmax[0], o));
            cmax[1] = fmaxf(cmax[1], __shfl_xor_sync(0xffffffffu, cmax[1], o));
        }
        float mn0 = fmaxf(m_run[0], cmax[0]);
        float mn1 = fmaxf(m_run[1], cmax[1]);
        float sc0 = __expf(m_run[0] - mn0);
        float sc1 = __expf(m_run[1] - mn1);
        m_run[0] = mn0; m_run[1] = mn1;

        float psum[2] = {0.f, 0.f};
#pragma unroll
        for (int nf = 0; nf < 16; nf++) {
            accS[nf][0] = __expf(accS[nf][0] - mn0);
            accS[nf][1] = __expf(accS[nf][1] - mn0);
            accS[nf][2] = __expf(accS[nf][2] - mn1);
            accS[nf][3] = __expf(accS[nf][3] - mn1);
            psum[0] += accS[nf][0] + accS[nf][1];
            psum[1] += accS[nf][2] + accS[nf][3];
        }
        l_t[0] = l_t[0] * sc0 + psum[0];
        l_t[1] = l_t[1] * sc1 + psum[1];

        if (t == 0) { sScale[jr] = sc0; sScale[jr + 8] = sc1; }
#pragma unroll
        for (int nf = 0; nf < 16; nf++) {
            int ic = nf * 8 + 2 * t;
            *(float2*)&sP[jr * PS + ic] =
                make_float2(rtf32(accS[nf][0]), rtf32(accS[nf][1]));
            *(float2*)&sP[(jr + 8) * PS + ic] =
                make_float2(rtf32(accS[nf][2]), rtf32(accS[nf][3]));
        }
        __syncthreads();

        // ---- PV: O[32 c][32 j] per warp; rescale then accumulate ----
#pragma unroll
        for (int nf = 0; nf < 4; nf++) {
            float s0 = sScale[wj * 32 + nf * 8 + 2 * t];
            float s1 = sScale[wj * 32 + nf * 8 + 2 * t + 1];
#pragma unroll
            for (int mf = 0; mf < 2; mf++) {
                accO[mf][nf][0] *= s0; accO[mf][nf][1] *= s1;
                accO[mf][nf][2] *= s0; accO[mf][nf][3] *= s1;
            }
        }
#pragma unroll
        for (int k0 = 0; k0 < 128; k0 += 8) {
            uint32_t af[2][4];
#pragma unroll
            for (int mf = 0; mf < 2; mf++) {
                int cr = wc * 32 + mf * 16 + g;
                af[mf][0] = __float_as_uint(sV[cr * VS + k0 + t]);
                af[mf][1] = __float_as_uint(sV[(cr + 8) * VS + k0 + t]);
                af[mf][2] = __float_as_uint(sV[cr * VS + k0 + t + 4]);
                af[mf][3] = __float_as_uint(sV[(cr + 8) * VS + k0 + t + 4]);
            }
#pragma unroll
            for (int nf = 0; nf < 4; nf++) {
                int jn = wj * 32 + nf * 8 + g;
                uint32_t b0 = __float_as_uint(sP[jn * PS + k0 + t]);
                uint32_t b1 = __float_as_uint(sP[jn * PS + k0 + t + 4]);
#pragma unroll
                for (int mf = 0; mf < 2; mf++)
                    MMA_TF32(accO[mf][nf][0], accO[mf][nf][1], accO[mf][nf][2], accO[mf][nf][3],
                             af[mf][0], af[mf][1], af[mf][2], af[mf][3], b0, b1);
            }
        }
        __syncthreads();
    }

    // ---- finalize: 1/l per row, broadcast, write g_ocl ----
#pragma unroll
    for (int o = 1; o <= 2; o <<= 1) {
        l_t[0] += __shfl_xor_sync(0xffffffffu, l_t[0], o);
        l_t[1] += __shfl_xor_sync(0xffffffffu, l_t[1], o);
    }
    if (t == 0) {
        sScale[wid * 16 + g]     = 1.f / l_t[0];
        sScale[wid * 16 + g + 8] = 1.f / l_t[1];
    }
    __syncthreads();

    const int n = m >> 2, hh = m & 3;
    const int b = n / 9, rem = n % 9;
    const int wh = rem / 3, ww = rem % 3;
#pragma unroll
    for (int nf = 0; nf < 4; nf++) {
#pragma unroll
        for (int e = 0; e < 2; e++) {
            const int jl = wj * 32 + nf * 8 + 2 * t + e;
            const float inv = sScale[jl];
            const int j = jt * 128 + jl;
            const int h = wh * 32 + (j >> 5), w = ww * 32 + (j & 31);
            float* dst = g_ocl + (((size_t)b * 98 + h + 1) * 98 + (w + 1)) * 256 + hh * 64;
#pragma unroll
            for (int mf = 0; mf < 2; mf++) {
                const int c0 = wc * 32 + mf * 16 + g;
                dst[c0]     = rtf32(accO[mf][nf][0 + e] * inv);
                dst[c0 + 8] = rtf32(accO[mf][nf][2 + e] * inv);
            }
        }
    }
}

// ===========================================================================
extern "C" void kernel_launch(void* const* d_in, const int* in_sizes, int n_in,
                              void* d_out, int out_size)
{
    (void)in_sizes; (void)n_in; (void)out_size;
    const float* x  = (const float*)d_in[0];
    const float* W1 = (const float*)d_in[1];
    const float* b1 = (const float*)d_in[2];
    const float* W2 = (const float*)d_in[3];
    const float* b2 = (const float*)d_in[4];
    float* out = (float*)d_out;

    const int CONV_SMEM = 2 * 2 * 128 * 36 * 4;   // 73728
    cudaFuncSetAttribute(conv_mma_kernel<512, 768, 0>,
                         cudaFuncAttributeMaxDynamicSharedMemorySize, CONV_SMEM);
    cudaFuncSetAttribute(conv_mma_kernel<256, 512, 1>,
                         cudaFuncAttributeMaxDynamicSharedMemorySize, CONV_SMEM);

    const int ATTN_SMEM = (128 * 68 + 128 * 68 + 64 * 132 + 128 * 132 + 128) * 4;
    cudaFuncSetAttribute(fused_attn_kernel,
                         cudaFuncAttributeMaxDynamicSharedMemorySize, ATTN_SMEM);

    // pack inputs / weights (tf32-rounded)
    fill_border_kernel<512><<<(2 * 388 * 128 + 255) / 256, 256>>>();
    fill_border_kernel<256><<<(2 * 388 * 64 + 255) / 256, 256>>>();
    pack_cl_kernel<<<dim3(96, 16, 2), 256>>>(x);
    repack_w_kernel<768, 512, 0><<<(9 * 768 * 512 + 255) / 256, 256>>>(W1);
    repack_w_kernel<512, 256, 1><<<(9 * 512 * 256 + 255) / 256, 256>>>(W2);

    // conv1 + ReLU -> packed Q/K/V (tf32 mma)
    conv_mma_kernel<512, 768, 0><<<dim3(144, 6), 256, CONV_SMEM>>>(b1, nullptr, nullptr);

    // fused attention -> g_ocl (channels-last conv2 input)
    fused_attn_kernel<<<dim3(8, 72), 256, ATTN_SMEM>>>();

    // conv2 + residual (tf32 mma)
    conv_mma_kernel<256, 512, 1><<<dim3(144, 4), 256, CONV_SMEM>>>(b2, x, out);
}

// round 5
// speedup vs baseline: 3.1012x; 1.0131x over previous
#include <cuda_runtime.h>
#include <math.h>
#include <stdint.h>

// ===========================================================================
// LocalAttention on sm_100 (portable PTX, tensor pipe via mma.sync tf32):
//   conv3x3(512->768)+ReLU  -> tf32 mma implicit GEMM (128co x 256px CTAs),
//                              epilogue packs Q(*0.125)/K [m][l][c], V [m][c][l]
//   fused flash-style windowed attention (64-i chunks, occupancy 2)
//                           -> writes conv2 input (padded channels-last)
//   conv3x3(256->512)+residual -> tf32 mma implicit GEMM
// ===========================================================================

// ------------------------------- scratch ----------------------------------
__device__ float g_kt [72 * 1024 * 64];      // K: [m][i][c]   (tf32-rounded)
__device__ float g_qt [72 * 1024 * 64];      // Q: [m][j][c]   (pre-scaled by 1/8)
__device__ float g_v  [72 * 64 * 1024];      // V: [m][c][i]
__device__ float g_xcl[2 * 98 * 98 * 512];   // padded channels-last input
__device__ float g_ocl[2 * 98 * 98 * 256];   // padded channels-last attn output
__device__ float g_w1p[9 * 768 * 512];       // W1 [s][co][ci], tf32-rounded
__device__ float g_w2p[9 * 512 * 256];       // W2 [s][co][ci]

// ------------------------------ helpers -----------------------------------
__device__ __forceinline__ uint32_t smem_u32(const void* p) {
    uint32_t a;
    asm("{ .reg .u64 t; cvta.to.shared.u64 t, %1; cvt.u32.u64 %0, t; }" : "=r"(a) : "l"(p));
    return a;
}
__device__ __forceinline__ float rtf32(float v) {
    uint32_t o;
    asm("cvt.rna.tf32.f32 %0, %1;" : "=r"(o) : "f"(v));
    return __uint_as_float(o);
}

#define CP_ASYNC16(sm, gm) \
    asm volatile("cp.async.cg.shared.global [%0], [%1], 16;" :: "r"(sm), "l"(gm))
#define CP_COMMIT() asm volatile("cp.async.commit_group;" ::: "memory")
#define CP_WAIT1()  asm volatile("cp.async.wait_group 1;" ::: "memory")
#define CP_WAIT0()  asm volatile("cp.async.wait_group 0;" ::: "memory")

#define MMA_TF32(c0,c1,c2,c3, a0,a1,a2,a3, b0,b1) \
    asm volatile("mma.sync.aligned.m16n8k8.row.col.f32.tf32.tf32.f32 " \
        "{%0,%1,%2,%3}, {%4,%5,%6,%7}, {%8,%9}, {%0,%1,%2,%3};" \
        : "+f"(c0), "+f"(c1), "+f"(c2), "+f"(c3) \
        : "r"(a0), "r"(a1), "r"(a2), "r"(a3), "r"(b0), "r"(b1))

// ===========================================================================
// Pack kernels
// ===========================================================================
template <int C>
__global__ void fill_border_kernel() {
    float* out = (C == 512) ? g_xcl : g_ocl;
    int idx = blockIdx.x * 256 + threadIdx.x;
    const int c4n = C / 4;
    const int total = 2 * 388 * c4n;
    if (idx >= total) return;
    int c4 = idx % c4n;
    int cell = (idx / c4n) % 388;
    int b = idx / (388 * c4n);
    int h, w;
    if (cell < 98)        { h = 0;  w = cell; }
    else if (cell < 196)  { h = 97; w = cell - 98; }
    else if (cell < 292)  { h = cell - 196 + 1; w = 0; }
    else                  { h = cell - 292 + 1; w = 97; }
    float4 z = make_float4(0.f, 0.f, 0.f, 0.f);
    ((float4*)&out[(((size_t)b * 98 + h) * 98 + w) * C])[c4] = z;
}

__global__ __launch_bounds__(256) void pack_cl_kernel(const float* __restrict__ in) {
    __shared__ float s[32][97];
    const int h = blockIdx.x, cig = blockIdx.y, b = blockIdx.z;
    const int tid = threadIdx.x;
    for (int e = tid; e < 32 * 96; e += 256) {
        int ci = e / 96, w = e % 96;
        s[ci][w] = in[(((size_t)b * 512 + cig * 32 + ci) * 96 + h) * 96 + w];
    }
    __syncthreads();
    for (int e = tid; e < 96 * 32; e += 256) {
        int w = e >> 5, ci = e & 31;
        g_xcl[(((size_t)b * 98 + h + 1) * 98 + (w + 1)) * 512 + cig * 32 + ci] = rtf32(s[ci][w]);
    }
}

template <int CO, int CI, int WHICH>
__global__ void repack_w_kernel(const float* __restrict__ W) {
    float* Wp = (WHICH == 0) ? g_w1p : g_w2p;
    int idx = blockIdx.x * 256 + threadIdx.x;
    const int total = 9 * CO * CI;
    if (idx >= total) return;
    int s = idx / (CO * CI);
    int rem = idx % (CO * CI);
    int co = rem / CI, ci = rem % CI;
    Wp[idx] = rtf32(W[((size_t)co * CI + ci) * 9 + s]);
}

// ===========================================================================
// tf32 mma.sync implicit-GEMM conv3x3.
// CTA: D[128 co x 256 px]; px tile = 8 rows x 32 cols. 8 warps (2M x 4N),
// warp tile 64co x 64px via m16n8k8 (4 m-frags x 8 n-frags).
// MODE 0: bias+ReLU -> tf32-rounded Q(*0.125)/K [m][l][c] and V [m][c][l].
// MODE 1: bias+residual -> out (fp32 exact epilogue).
// ===========================================================================
template <int CIN, int COUT, int MODE>
__global__ void __launch_bounds__(256, 1)
conv_mma_kernel(const float* __restrict__ bias,
                const float* __restrict__ resid,
                float* __restrict__ out)
{
    constexpr int NIT = 9 * CIN / 32;
    constexpr int ABUF = 128 * 36;
    constexpr int BBUF = 256 * 36;
    constexpr int BUF  = ABUF + BBUF;

    const float* __restrict__ Wp  = (MODE == 0) ? g_w1p : g_w2p;
    const float* __restrict__ xcl = (MODE == 0) ? g_xcl : g_ocl;
    const int XC = (MODE == 0) ? 512 : 256;

    extern __shared__ float smf[];
    const uint32_t sb = smem_u32(smf);

    const int tid  = threadIdx.x;
    const int wid  = tid >> 5;
    const int lane = tid & 31;
    const int g = lane >> 2;
    const int t = lane & 3;
    const int wm = wid >> 2;              // 0..1 : co 64-half
    const int wn = wid & 3;               // 0..3 : px 64-quarter

    const int pt = blockIdx.x;            // 72 = b(2) x 12 rowbands x 3 colbands
    const int b  = pt / 36;
    const int r  = pt % 36;
    const int h0 = (r / 3) * 8;
    const int w0 = (r % 3) * 32;
    const int co0 = blockIdx.y * 128;

    const int arow  = tid >> 1;           // A: 2 threads per 128B row
    const int ahalf = (tid & 1) * 64;
    const int bpr = tid >> 5, bpc = tid & 31;   // B: 1 thread per 128B row

    auto load_stage = [&](int it, int buf) {
        const int s   = it / (CIN / 32);
        const int ci0 = (it % (CIN / 32)) * 32;
        const int kh = s / 3, kw = s % 3;
        const uint32_t abase = sb + (buf * BUF + arow * 36) * 4 + ahalf;
        const char* ga = (const char*)(Wp + ((size_t)s * COUT + co0 + arow) * CIN + ci0) + ahalf;
#pragma unroll
        for (int i = 0; i < 4; i++) CP_ASYNC16(abase + i * 16, ga + i * 16);
        const uint32_t bbase = sb + (buf * BUF + ABUF + tid * 36) * 4;
        const char* gb = (const char*)
            (xcl + (((size_t)(b * 98 + h0 + bpr + kh)) * 98 + (w0 + bpc + kw)) * XC + ci0);
#pragma unroll
        for (int i = 0; i < 8; i++) CP_ASYNC16(bbase + i * 16, gb + i * 16);
        CP_COMMIT();
    };

    float acc[4][8][4];
#pragma unroll
    for (int mf = 0; mf < 4; mf++)
#pragma unroll
        for (int nf = 0; nf < 8; nf++)
#pragma unroll
            for (int e = 0; e < 4; e++) acc[mf][nf][e] = 0.f;

    load_stage(0, 0);

    for (int it = 0; it < NIT; ++it) {
        const int buf = it & 1;
        if (it + 1 < NIT) { load_stage(it + 1, buf ^ 1); CP_WAIT1(); }
        else              { CP_WAIT0(); }
        __syncthreads();

        const float* Sa = smf + buf * BUF;
        const float* Sb = Sa + ABUF;
#pragma unroll
        for (int k0 = 0; k0 < 32; k0 += 8) {
            uint32_t bf[8][2];
#pragma unroll
            for (int nf = 0; nf < 8; nf++) {
                int n = wn * 64 + nf * 8 + g;
                bf[nf][0] = __float_as_uint(Sb[n * 36 + k0 + t]);
                bf[nf][1] = __float_as_uint(Sb[n * 36 + k0 + t + 4]);
            }
#pragma unroll
            for (int mf = 0; mf < 4; mf++) {
                int m = wm * 64 + mf * 16 + g;
                uint32_t a0 = __float_as_uint(Sa[m * 36 + k0 + t]);
                uint32_t a1 = __float_as_uint(Sa[(m + 8) * 36 + k0 + t]);
                uint32_t a2 = __float_as_uint(Sa[m * 36 + k0 + t + 4]);
                uint32_t a3 = __float_as_uint(Sa[(m + 8) * 36 + k0 + t + 4]);
#pragma unroll
                for (int nf = 0; nf < 8; nf++)
                    MMA_TF32(acc[mf][nf][0], acc[mf][nf][1], acc[mf][nf][2], acc[mf][nf][3],
                             a0, a1, a2, a3, bf[nf][0], bf[nf][1]);
            }
        }
        __syncthreads();
    }

    // ----------------------------- epilogue -------------------------------
#pragma unroll
    for (int mf = 0; mf < 4; mf++) {
#pragma unroll
        for (int half8 = 0; half8 < 2; half8++) {
            const int co_g = co0 + wm * 64 + mf * 16 + g + half8 * 8;
            const float bv = __ldg(&bias[co_g]);
            if (MODE == 0) {
                const int part = co_g >> 8;          // 0=K 1=V 2=Q
                const int hh   = (co_g >> 6) & 3;
                const int cc   = co_g & 63;
                const int mm   = ((b * 9 + (h0 >> 5) * 3 + (w0 >> 5)) << 2) + hh;
                const float qs = (part == 2) ? 0.125f : 1.0f;
#pragma unroll
                for (int nf = 0; nf < 8; nf++) {
                    const int px0 = wn * 64 + nf * 8 + 2 * t;
                    float v0 = rtf32(qs * fmaxf(acc[mf][nf][half8 * 2 + 0] + bv, 0.f));
                    float v1 = rtf32(qs * fmaxf(acc[mf][nf][half8 * 2 + 1] + bv, 0.f));
                    const int l0 = ((h0 & 31) + (px0 >> 5)) * 32 + (px0 & 31);
                    if (part == 1) {
                        float* dst = g_v + ((size_t)(mm * 64 + cc)) * 1024 + l0;
                        *(float2*)dst = make_float2(v0, v1);
                    } else {
                        float* dq = (part ? g_qt : g_kt) + ((size_t)mm * 1024 + l0) * 64 + cc;
                        dq[0]  = v0;
                        dq[64] = v1;
                    }
                }
            } else {
#pragma unroll
                for (int nf = 0; nf < 8; nf++) {
                    const int px0 = wn * 64 + nf * 8 + 2 * t;
                    const int h = h0 + (px0 >> 5), w = w0 + (px0 & 31);
                    const size_t idx = (((size_t)(b * 512 + co_g) * 96) + h) * 96 + w;
                    float2 rv = *(const float2*)(resid + idx);
                    float2 v;
                    v.x = rv.x + bv + acc[mf][nf][half8 * 2 + 0];
                    v.y = rv.y + bv + acc[mf][nf][half8 * 2 + 1];
                    *(float2*)(out + idx) = v;
                }
            }
        }
    }
}

// ===========================================================================
// Fused flash-style attention. CTA = (m, 128-j tile). 256 threads, 8 warps.
// K/V streamed in 64-i chunks (16 chunks) -> 105KB smem -> occupancy 2.
//   QK: warp = 16 j x 64 i  (softmax rows stay in one warp quad)
//   PV: warp = 32 c x 32 j
// Q is pre-scaled by 1/8. Epilogue writes g_ocl (channels-last, tf32-rounded).
// ===========================================================================
__global__ void __launch_bounds__(256, 2) fused_attn_kernel()
{
    constexpr int QS = 68, KS = 68, VS = 68, PS = 68;
    extern __shared__ float sm[];
    float* sQ = sm;                       // [128][68]
    float* sK = sQ + 128 * QS;            // [64][68]
    float* sV = sK + 64 * KS;             // [64][68]
    float* sP = sV + 64 * VS;             // [128][68]
    float* sScale = sP + 128 * PS;        // [128]

    const int m  = blockIdx.y;
    const int jt = blockIdx.x;            // 0..7
    const int tid = threadIdx.x, wid = tid >> 5, lane = tid & 31;
    const int g = lane >> 2, t = lane & 3;
    const int wc = wid >> 2;              // PV c-half (0..1)
    const int wj = wid & 3;               // PV j-quarter (0..3)

    // ---- load Q tile [128 j][64 c] ----
    {
        const uint32_t sqb = smem_u32(sQ);
        const char* Qg = (const char*)(g_qt + ((size_t)m * 1024 + jt * 128) * 64);
        for (int e = tid; e < 2048; e += 256) {
            int r = e >> 4, c = e & 15;
            CP_ASYNC16(sqb + (r * QS + c * 4) * 4, Qg + (r * 64 + c * 4) * 4);
        }
    }

    float accO[2][4][4];
#pragma unroll
    for (int mf = 0; mf < 2; mf++)
#pragma unroll
        for (int nf = 0; nf < 4; nf++)
#pragma unroll
            for (int e = 0; e < 4; e++) accO[mf][nf][e] = 0.f;

    float m_run[2] = {-1e30f, -1e30f};
    float l_t[2]   = {0.f, 0.f};

    const uint32_t skb = smem_u32(sK), svb = smem_u32(sV);
    const int jr = wid * 16 + g;          // QK row (and +8)

    for (int ch = 0; ch < 16; ch++) {
        const int i0 = ch * 64;
        // ---- load K chunk [64 i][64 c], V chunk [64 c][64 i] ----
        const char* Kg = (const char*)(g_kt + ((size_t)m * 1024 + i0) * 64);
        const char* Vg = (const char*)(g_v + (size_t)m * 64 * 1024 + i0);
        for (int e = tid; e < 1024; e += 256) {
            int r = e >> 4, c = e & 15;
            CP_ASYNC16(skb + (r * KS + c * 4) * 4, Kg + (r * 64 + c * 4) * 4);
        }
        for (int e = tid; e < 1024; e += 256) {
            int r = e >> 4, c = e & 15;
            CP_ASYNC16(svb + (r * VS + c * 4) * 4, Vg + (r * 1024 + c * 4) * 4);
        }
        CP_COMMIT();
        CP_WAIT0();
        __syncthreads();

        // ---- QK: S[16 j][64 i] per warp ----
        float accS[8][4];
#pragma unroll
        for (int nf = 0; nf < 8; nf++)
#pragma unroll
            for (int e = 0; e < 4; e++) accS[nf][e] = 0.f;

#pragma unroll
        for (int k0 = 0; k0 < 64; k0 += 8) {
            uint32_t a0 = __float_as_uint(sQ[jr * QS + k0 + t]);
            uint32_t a1 = __float_as_uint(sQ[(jr + 8) * QS + k0 + t]);
            uint32_t a2 = __float_as_uint(sQ[jr * QS + k0 + t + 4]);
            uint32_t a3 = __float_as_uint(sQ[(jr + 8) * QS + k0 + t + 4]);
#pragma unroll
            for (int nf = 0; nf < 8; nf++) {
                int n = nf * 8 + g;
                uint32_t b0 = __float_as_uint(sK[n * KS + k0 + t]);
                uint32_t b1 = __float_as_uint(sK[n * KS + k0 + t + 4]);
                MMA_TF32(accS[nf][0], accS[nf][1], accS[nf][2], accS[nf][3],
                         a0, a1, a2, a3, b0, b1);
            }
        }

        // ---- online softmax over i (cols), rows jr / jr+8 ----
        float cmax[2] = {-1e30f, -1e30f};
#pragma unroll
        for (int nf = 0; nf < 8; nf++) {
            cmax[0] = fmaxf(cmax[0], fmaxf(accS[nf][0], accS[nf][1]));
            cmax[1] = fmaxf(cmax[1], fmaxf(accS[nf][2], accS[nf][3]));
        }
#pragma unroll
        for (int o = 1; o <= 2; o <<= 1) {
            cmax[0] = fmaxf(cmax[0], __shfl_xor_sync(0xffffffffu, cmax[0], o));
            cmax[1] = fmaxf(cmax[1], __shfl_xor_sync(0xffffffffu, cmax[1], o));
        }
        float mn0 = fmaxf(m_run[0], cmax[0]);
        float mn1 = fmaxf(m_run[1], cmax[1]);
        float sc0 = __expf(m_run[0] - mn0);
        float sc1 = __expf(m_run[1] - mn1);
        m_run[0] = mn0; m_run[1] = mn1;

        float psum[2] = {0.f, 0.f};
#pragma unroll
        for (int nf = 0; nf < 8; nf++) {
            accS[nf][0] = __expf(accS[nf][0] - mn0);
            accS[nf][1] = __expf(accS[nf][1] - mn0);
            accS[nf][2] = __expf(accS[nf][2] - mn1);
            accS[nf][3] = __expf(accS[nf][3] - mn1);
            psum[0] += accS[nf][0] + accS[nf][1];
            psum[1] += accS[nf][2] + accS[nf][3];
        }
        l_t[0] = l_t[0] * sc0 + psum[0];
        l_t[1] = l_t[1] * sc1 + psum[1];

        if (t == 0) { sScale[jr] = sc0; sScale[jr + 8] = sc1; }
#pragma unroll
        for (int nf = 0; nf < 8; nf++) {
            int ic = nf * 8 + 2 * t;
            *(float2*)&sP[jr * PS + ic] =
                make_float2(rtf32(accS[nf][0]), rtf32(accS[nf][1]));
            *(float2*)&sP[(jr + 8) * PS + ic] =
                make_float2(rtf32(accS[nf][2]), rtf32(accS[nf][3]));
        }
        __syncthreads();

        // ---- PV: O[32 c][32 j] per warp; rescale then accumulate ----
#pragma unroll
        for (int nf = 0; nf < 4; nf++) {
            float s0 = sScale[wj * 32 + nf * 8 + 2 * t];
            float s1 = sScale[wj * 32 + nf * 8 + 2 * t + 1];
#pragma unroll
            for (int mf = 0; mf < 2; mf++) {
                accO[mf][nf][0] *= s0; accO[mf][nf][1] *= s1;
                accO[mf][nf][2] *= s0; accO[mf][nf][3] *= s1;
            }
        }
#pragma unroll
        for (int k0 = 0; k0 < 64; k0 += 8) {
            uint32_t af[2][4];
#pragma unroll
            for (int mf = 0; mf < 2; mf++) {
                int cr = wc * 32 + mf * 16 + g;
                af[mf][0] = __float_as_uint(sV[cr * VS + k0 + t]);
                af[mf][1] = __float_as_uint(sV[(cr + 8) * VS + k0 + t]);
                af[mf][2] = __float_as_uint(sV[cr * VS + k0 + t + 4]);
                af[mf][3] = __float_as_uint(sV[(cr + 8) * VS + k0 + t + 4]);
            }
#pragma unroll
            for (int nf = 0; nf < 4; nf++) {
                int jn = wj * 32 + nf * 8 + g;
                uint32_t b0 = __float_as_uint(sP[jn * PS + k0 + t]);
                uint32_t b1 = __float_as_uint(sP[jn * PS + k0 + t + 4]);
#pragma unroll
                for (int mf = 0; mf < 2; mf++)
                    MMA_TF32(accO[mf][nf][0], accO[mf][nf][1], accO[mf][nf][2], accO[mf][nf][3],
                             af[mf][0], af[mf][1], af[mf][2], af[mf][3], b0, b1);
            }
        }
        __syncthreads();
    }

    // ---- finalize: 1/l per row, broadcast, write g_ocl ----
#pragma unroll
    for (int o = 1; o <= 2; o <<= 1) {
        l_t[0] += __shfl_xor_sync(0xffffffffu, l_t[0], o);
        l_t[1] += __shfl_xor_sync(0xffffffffu, l_t[1], o);
    }
    if (t == 0) {
        sScale[jr]     = 1.f / l_t[0];
        sScale[jr + 8] = 1.f / l_t[1];
    }
    __syncthreads();

    const int n = m >> 2, hh = m & 3;
    const int b = n / 9, rem = n % 9;
    const int wh = rem / 3, ww = rem % 3;
#pragma unroll
    for (int nf = 0; nf < 4; nf++) {
#pragma unroll
        for (int e = 0; e < 2; e++) {
            const int jl = wj * 32 + nf * 8 + 2 * t + e;
            const float inv = sScale[jl];
            const int j = jt * 128 + jl;
            const int h = wh * 32 + (j >> 5), w = ww * 32 + (j & 31);
            float* dst = g_ocl + (((size_t)b * 98 + h + 1) * 98 + (w + 1)) * 256 + hh * 64;
#pragma unroll
            for (int mf = 0; mf < 2; mf++) {
                const int c0 = wc * 32 + mf * 16 + g;
                dst[c0]     = rtf32(accO[mf][nf][0 + e] * inv);
                dst[c0 + 8] = rtf32(accO[mf][nf][2 + e] * inv);
            }
        }
    }
}

// ===========================================================================
extern "C" void kernel_launch(void* const* d_in, const int* in_sizes, int n_in,
                              void* d_out, int out_size)
{
    (void)in_sizes; (void)n_in; (void)out_size;
    const float* x  = (const float*)d_in[0];
    const float* W1 = (const float*)d_in[1];
    const float* b1 = (const float*)d_in[2];
    const float* W2 = (const float*)d_in[3];
    const float* b2 = (const float*)d_in[4];
    float* out = (float*)d_out;

    const int CONV_SMEM = 2 * (128 + 256) * 36 * 4;   // 110592
    cudaFuncSetAttribute(conv_mma_kernel<512, 768, 0>,
                         cudaFuncAttributeMaxDynamicSharedMemorySize, CONV_SMEM);
    cudaFuncSetAttribute(conv_mma_kernel<256, 512, 1>,
                         cudaFuncAttributeMaxDynamicSharedMemorySize, CONV_SMEM);

    const int ATTN_SMEM = (128 * 68 + 64 * 68 + 64 * 68 + 128 * 68 + 128) * 4;  // 104960
    cudaFuncSetAttribute(fused_attn_kernel,
                         cudaFuncAttributeMaxDynamicSharedMemorySize, ATTN_SMEM);

    // pack inputs / weights (tf32-rounded)
    fill_border_kernel<512><<<(2 * 388 * 128 + 255) / 256, 256>>>();
    fill_border_kernel<256><<<(2 * 388 * 64 + 255) / 256, 256>>>();
    pack_cl_kernel<<<dim3(96, 16, 2), 256>>>(x);
    repack_w_kernel<768, 512, 0><<<(9 * 768 * 512 + 255) / 256, 256>>>(W1);
    repack_w_kernel<512, 256, 1><<<(9 * 512 * 256 + 255) / 256, 256>>>(W2);

    // conv1 + ReLU -> packed Q/K/V (tf32 mma)
    conv_mma_kernel<512, 768, 0><<<dim3(72, 6), 256, CONV_SMEM>>>(b1, nullptr, nullptr);

    // fused attention -> g_ocl (channels-last conv2 input)
    fused_attn_kernel<<<dim3(8, 72), 256, ATTN_SMEM>>>();

    // conv2 + residual (tf32 mma)
    conv_mma_kernel<256, 512, 1><<<dim3(72, 4), 256, CONV_SMEM>>>(b2, x, out);
}

// round 6
// speedup vs baseline: 5.7434x; 1.8520x over previous
#include <cuda_runtime.h>
#include <cuda_fp16.h>
#include <math.h>
#include <stdint.h>

// ===========================================================================
// LocalAttention on sm_100 (portable PTX; tensor pipe via mma.sync f16.f32):
//   conv3x3(512->768)+ReLU  -> fp16 m16n8k16 implicit GEMM, packs Q(*1/8)/K/V
//   fused flash-style windowed attention (fp16 operands, fp32 softmax/accum)
//   conv3x3(256->512)+residual -> fp16 m16n8k16 implicit GEMM (fp32 epilogue)
// ===========================================================================

// ------------------------------- scratch ----------------------------------
__device__ __half g_kt [72 * 1024 * 64];      // K: [m][i][c]
__device__ __half g_qt [72 * 1024 * 64];      // Q: [m][j][c] (pre-scaled 1/8)
__device__ __half g_v  [72 * 64 * 1024];      // V: [m][c][i]
__device__ __half g_xcl[2 * 98 * 98 * 512];   // padded channels-last input
__device__ __half g_ocl[2 * 98 * 98 * 256];   // padded channels-last attn out
__device__ __half g_w1p[9 * 768 * 512];       // W1 [s][co][ci]
__device__ __half g_w2p[9 * 512 * 256];       // W2 [s][co][ci]

// ------------------------------ helpers -----------------------------------
__device__ __forceinline__ uint32_t smem_u32(const void* p) {
    uint32_t a;
    asm("{ .reg .u64 t; cvta.to.shared.u64 t, %1; cvt.u32.u64 %0, t; }" : "=r"(a) : "l"(p));
    return a;
}

#define CP_ASYNC16(sm, gm) \
    asm volatile("cp.async.cg.shared.global [%0], [%1], 16;" :: "r"(sm), "l"(gm))
#define CP_COMMIT() asm volatile("cp.async.commit_group;" ::: "memory")
#define CP_WAIT1()  asm volatile("cp.async.wait_group 1;" ::: "memory")
#define CP_WAIT0()  asm volatile("cp.async.wait_group 0;" ::: "memory")

// fp16 mma, fp32 accum. C layout: c0=(g,2t) c1=(g,2t+1) c2=(g+8,2t) c3=(g+8,2t+1)
#define MMA_F16(c0,c1,c2,c3, a0,a1,a2,a3, b0,b1) \
    asm volatile("mma.sync.aligned.m16n8k16.row.col.f32.f16.f16.f32 " \
        "{%0,%1,%2,%3}, {%4,%5,%6,%7}, {%8,%9}, {%0,%1,%2,%3};" \
        : "+f"(c0), "+f"(c1), "+f"(c2), "+f"(c3) \
        : "r"(a0), "r"(a1), "r"(a2), "r"(a3), "r"(b0), "r"(b1))

// ===========================================================================
// Pack kernels
// ===========================================================================
template <int C>
__global__ void fill_border_kernel() {
    __half* out = (C == 512) ? g_xcl : g_ocl;
    int idx = blockIdx.x * 256 + threadIdx.x;
    const int un = C / 8;                       // 16B units per pixel
    const int total = 2 * 388 * un;
    if (idx >= total) return;
    int u = idx % un;
    int cell = (idx / un) % 388;
    int b = idx / (388 * un);
    int h, w;
    if (cell < 98)        { h = 0;  w = cell; }
    else if (cell < 196)  { h = 97; w = cell - 98; }
    else if (cell < 292)  { h = cell - 196 + 1; w = 0; }
    else                  { h = cell - 292 + 1; w = 97; }
    uint4 z = make_uint4(0u, 0u, 0u, 0u);
    ((uint4*)&out[(((size_t)b * 98 + h) * 98 + w) * C])[u] = z;
}

__global__ __launch_bounds__(256) void pack_cl_kernel(const float* __restrict__ in) {
    __shared__ float s[32][97];
    const int h = blockIdx.x, cig = blockIdx.y, b = blockIdx.z;
    const int tid = threadIdx.x;
    for (int e = tid; e < 32 * 96; e += 256) {
        int ci = e / 96, w = e % 96;
        s[ci][w] = in[(((size_t)b * 512 + cig * 32 + ci) * 96 + h) * 96 + w];
    }
    __syncthreads();
    for (int e = tid; e < 96 * 32; e += 256) {
        int w = e >> 5, ci = e & 31;
        g_xcl[(((size_t)b * 98 + h + 1) * 98 + (w + 1)) * 512 + cig * 32 + ci] =
            __float2half_rn(s[ci][w]);
    }
}

template <int CO, int CI, int WHICH>
__global__ void repack_w_kernel(const float* __restrict__ W) {
    __half* Wp = (WHICH == 0) ? g_w1p : g_w2p;
    int idx = blockIdx.x * 256 + threadIdx.x;
    const int total = 9 * CO * CI;
    if (idx >= total) return;
    int s = idx / (CO * CI);
    int rem = idx % (CO * CI);
    int co = rem / CI, ci = rem % CI;
    Wp[idx] = __float2half_rn(W[((size_t)co * CI + ci) * 9 + s]);
}

// ===========================================================================
// fp16 mma.sync implicit-GEMM conv3x3.
// CTA: D[128 co x 256 px]; px tile = 8 rows x 32 cols. 8 warps (2M x 4N),
// warp tile 64co x 64px via m16n8k16 (4 m-frags x 8 n-frags, 2 k-steps/chunk).
// smem: A[128][40] + B[256][40] halves per buffer, K-chunk = 32 ci, double buf.
// MODE 0: bias+ReLU -> fp16 Q(*0.125)/K [m][l][c] and V [m][c][l].
// MODE 1: bias+residual -> out (fp32 exact epilogue).
// ===========================================================================
template <int CIN, int COUT, int MODE>
__global__ void __launch_bounds__(256, 1)
conv_mma_kernel(const float* __restrict__ bias,
                const float* __restrict__ resid,
                float* __restrict__ out)
{
    constexpr int NIT  = 9 * CIN / 32;
    constexpr int AST  = 40;                 // halves per row
    constexpr int ABUF = 128 * AST;          // halves
    constexpr int BBUF = 256 * AST;
    constexpr int BUF  = ABUF + BBUF;

    const __half* __restrict__ Wp  = (MODE == 0) ? g_w1p : g_w2p;
    const __half* __restrict__ xcl = (MODE == 0) ? g_xcl : g_ocl;
    const int XC = (MODE == 0) ? 512 : 256;

    extern __shared__ __half smh[];
    const uint32_t sb = smem_u32(smh);

    const int tid  = threadIdx.x;
    const int wid  = tid >> 5;
    const int lane = tid & 31;
    const int g = lane >> 2;
    const int t = lane & 3;
    const int wm = wid >> 2;              // 0..1 : co 64-half
    const int wn = wid & 3;               // 0..3 : px 64-quarter

    const int pt = blockIdx.x;            // 72 = b(2) x 12 rowbands x 3 colbands
    const int b  = pt / 36;
    const int r  = pt % 36;
    const int h0 = (r / 3) * 8;
    const int w0 = (r % 3) * 32;
    const int co0 = blockIdx.y * 128;

    const int arow  = tid >> 1;                 // A: 2 threads per 64B row
    const int ahalf = (tid & 1) * 32;           // byte offset within row
    const int bpr = tid >> 5, bpc = tid & 31;   // B: 1 thread per 64B row

    auto load_stage = [&](int it, int buf) {
        const int s   = it / (CIN / 32);
        const int ci0 = (it % (CIN / 32)) * 32;
        const int kh = s / 3, kw = s % 3;
        const uint32_t abase = sb + (buf * BUF + arow * AST) * 2 + ahalf;
        const char* ga = (const char*)(Wp + ((size_t)s * COUT + co0 + arow) * CIN + ci0) + ahalf;
        CP_ASYNC16(abase, ga);
        CP_ASYNC16(abase + 16, ga + 16);
        const uint32_t bbase = sb + (buf * BUF + ABUF + tid * AST) * 2;
        const char* gb = (const char*)
            (xcl + (((size_t)(b * 98 + h0 + bpr + kh)) * 98 + (w0 + bpc + kw)) * XC + ci0);
#pragma unroll
        for (int i = 0; i < 4; i++) CP_ASYNC16(bbase + i * 16, gb + i * 16);
        CP_COMMIT();
    };

    float acc[4][8][4];
#pragma unroll
    for (int mf = 0; mf < 4; mf++)
#pragma unroll
        for (int nf = 0; nf < 8; nf++)
#pragma unroll
            for (int e = 0; e < 4; e++) acc[mf][nf][e] = 0.f;

    load_stage(0, 0);

    for (int it = 0; it < NIT; ++it) {
        const int buf = it & 1;
        if (it + 1 < NIT) { load_stage(it + 1, buf ^ 1); CP_WAIT1(); }
        else              { CP_WAIT0(); }
        __syncthreads();

        const __half* Sa = smh + buf * BUF;
        const __half* Sb = Sa + ABUF;
#pragma unroll
        for (int ks = 0; ks < 2; ks++) {
            const int k0 = ks * 16;
            uint32_t bf[8][2];
#pragma unroll
            for (int nf = 0; nf < 8; nf++) {
                int n = wn * 64 + nf * 8 + g;
                bf[nf][0] = *(const uint32_t*)&Sb[n * AST + k0 + 2 * t];
                bf[nf][1] = *(const uint32_t*)&Sb[n * AST + k0 + 2 * t + 8];
            }
#pragma unroll
            for (int mf = 0; mf < 4; mf++) {
                int m = wm * 64 + mf * 16 + g;
                uint32_t a0 = *(const uint32_t*)&Sa[m * AST + k0 + 2 * t];
                uint32_t a1 = *(const uint32_t*)&Sa[(m + 8) * AST + k0 + 2 * t];
                uint32_t a2 = *(const uint32_t*)&Sa[m * AST + k0 + 2 * t + 8];
                uint32_t a3 = *(const uint32_t*)&Sa[(m + 8) * AST + k0 + 2 * t + 8];
#pragma unroll
                for (int nf = 0; nf < 8; nf++)
                    MMA_F16(acc[mf][nf][0], acc[mf][nf][1], acc[mf][nf][2], acc[mf][nf][3],
                            a0, a1, a2, a3, bf[nf][0], bf[nf][1]);
            }
        }
        __syncthreads();
    }

    // ----------------------------- epilogue -------------------------------
#pragma unroll
    for (int mf = 0; mf < 4; mf++) {
#pragma unroll
        for (int half8 = 0; half8 < 2; half8++) {
            const int co_g = co0 + wm * 64 + mf * 16 + g + half8 * 8;
            const float bv = __ldg(&bias[co_g]);
            if (MODE == 0) {
                const int part = co_g >> 8;          // 0=K 1=V 2=Q
                const int hh   = (co_g >> 6) & 3;
                const int cc   = co_g & 63;
                const int mm   = ((b * 9 + (h0 >> 5) * 3 + (w0 >> 5)) << 2) + hh;
                const float qs = (part == 2) ? 0.125f : 1.0f;
#pragma unroll
                for (int nf = 0; nf < 8; nf++) {
                    const int px0 = wn * 64 + nf * 8 + 2 * t;
                    float v0 = qs * fmaxf(acc[mf][nf][half8 * 2 + 0] + bv, 0.f);
                    float v1 = qs * fmaxf(acc[mf][nf][half8 * 2 + 1] + bv, 0.f);
                    const int l0 = ((h0 & 31) + (px0 >> 5)) * 32 + (px0 & 31);
                    if (part == 1) {
                        __half2* dst = (__half2*)(g_v + ((size_t)(mm * 64 + cc)) * 1024 + l0);
                        *dst = __floats2half2_rn(v0, v1);
                    } else {
                        __half* dq = (part ? g_qt : g_kt) + ((size_t)mm * 1024 + l0) * 64 + cc;
                        dq[0]  = __float2half_rn(v0);
                        dq[64] = __float2half_rn(v1);
                    }
                }
            } else {
#pragma unroll
                for (int nf = 0; nf < 8; nf++) {
                    const int px0 = wn * 64 + nf * 8 + 2 * t;
                    const int h = h0 + (px0 >> 5), w = w0 + (px0 & 31);
                    const size_t idx = (((size_t)(b * 512 + co_g) * 96) + h) * 96 + w;
                    float2 rv = *(const float2*)(resid + idx);
                    float2 v;
                    v.x = rv.x + bv + acc[mf][nf][half8 * 2 + 0];
                    v.y = rv.y + bv + acc[mf][nf][half8 * 2 + 1];
                    *(float2*)(out + idx) = v;
                }
            }
        }
    }
}

// ===========================================================================
// Fused flash-style attention, fp16 operands. CTA = (m, 128-j tile).
// 256 threads, 8 warps; K/V in 64-i chunks (16 chunks); smem ~55KB -> occ 2.
//   QK: warp = 16 j x 64 i  (m16n8k16, 4 k-steps over c=64)
//   PV: warp = 32 c x 32 j  (k = i, 4 k-steps over 64)
// Q pre-scaled by 1/8. Softmax and O accum fp32. Writes g_ocl (fp16 CL).
// ===========================================================================
__global__ void __launch_bounds__(256, 2) fused_attn_kernel()
{
    constexpr int ST = 72;                 // halves per row (pad 64 -> 72)
    extern __shared__ __half sh[];
    __half* sQ = sh;                       // [128][72]
    __half* sK = sQ + 128 * ST;            // [64][72]
    __half* sV = sK + 64 * ST;             // [64][72]
    __half* sP = sV + 64 * ST;             // [128][72]  (P[j][i])
    float* sScale = (float*)(sP + 128 * ST);   // [128]

    const int m  = blockIdx.y;
    const int jt = blockIdx.x;            // 0..7
    const int tid = threadIdx.x, wid = tid >> 5, lane = tid & 31;
    const int g = lane >> 2, t = lane & 3;
    const int wc = wid >> 2;              // PV c-half (0..1)
    const int wj = wid & 3;               // PV j-quarter (0..3)

    // ---- load Q tile [128 j][64 c] halves (128B rows) ----
    {
        const uint32_t sqb = smem_u32(sQ);
        const char* Qg = (const char*)(g_qt + ((size_t)m * 1024 + jt * 128) * 64);
        for (int e = tid; e < 1024; e += 256) {
            int r = e >> 3, u = e & 7;
            CP_ASYNC16(sqb + (r * ST) * 2 + u * 16, Qg + r * 128 + u * 16);
        }
    }

    float accO[2][4][4];
#pragma unroll
    for (int mf = 0; mf < 2; mf++)
#pragma unroll
        for (int nf = 0; nf < 4; nf++)
#pragma unroll
            for (int e = 0; e < 4; e++) accO[mf][nf][e] = 0.f;

    float m_run[2] = {-1e30f, -1e30f};
    float l_t[2]   = {0.f, 0.f};

    const uint32_t skb = smem_u32(sK), svb = smem_u32(sV);
    const int jr = wid * 16 + g;          // QK row (and +8)

    for (int ch = 0; ch < 16; ch++) {
        const int i0 = ch * 64;
        // ---- load K chunk [64 i][64 c], V chunk [64 c][64 i] (halves) ----
        const char* Kg = (const char*)(g_kt + ((size_t)m * 1024 + i0) * 64);
        const char* Vg = (const char*)(g_v + (size_t)m * 64 * 1024 + i0);
        for (int e = tid; e < 512; e += 256) {
            int r = e >> 3, u = e & 7;
            CP_ASYNC16(skb + (r * ST) * 2 + u * 16, Kg + r * 128 + u * 16);
        }
        for (int e = tid; e < 512; e += 256) {
            int r = e >> 3, u = e & 7;
            CP_ASYNC16(svb + (r * ST) * 2 + u * 16, Vg + r * 2048 + u * 16);
        }
        CP_COMMIT();
        CP_WAIT0();
        __syncthreads();

        // ---- QK: S[16 j][64 i] per warp (k = c = 64, 4 k-steps) ----
        float accS[8][4];
#pragma unroll
        for (int nf = 0; nf < 8; nf++)
#pragma unroll
            for (int e = 0; e < 4; e++) accS[nf][e] = 0.f;

#pragma unroll
        for (int ks = 0; ks < 4; ks++) {
            const int k0 = ks * 16;
            uint32_t a0 = *(const uint32_t*)&sQ[jr * ST + k0 + 2 * t];
            uint32_t a1 = *(const uint32_t*)&sQ[(jr + 8) * ST + k0 + 2 * t];
            uint32_t a2 = *(const uint32_t*)&sQ[jr * ST + k0 + 2 * t + 8];
            uint32_t a3 = *(const uint32_t*)&sQ[(jr + 8) * ST + k0 + 2 * t + 8];
#pragma unroll
            for (int nf = 0; nf < 8; nf++) {
                int n = nf * 8 + g;
                uint32_t b0 = *(const uint32_t*)&sK[n * ST + k0 + 2 * t];
                uint32_t b1 = *(const uint32_t*)&sK[n * ST + k0 + 2 * t + 8];
                MMA_F16(accS[nf][0], accS[nf][1], accS[nf][2], accS[nf][3],
                        a0, a1, a2, a3, b0, b1);
            }
        }

        // ---- online softmax over i (cols), rows jr / jr+8 ----
        float cmax[2] = {-1e30f, -1e30f};
#pragma unroll
        for (int nf = 0; nf < 8; nf++) {
            cmax[0] = fmaxf(cmax[0], fmaxf(accS[nf][0], accS[nf][1]));
            cmax[1] = fmaxf(cmax[1], fmaxf(accS[nf][2], accS[nf][3]));
        }
#pragma unroll
        for (int o = 1; o <= 2; o <<= 1) {
            cmax[0] = fmaxf(cmax[0], __shfl_xor_sync(0xffffffffu, cmax[0], o));
            cmax[1] = fmaxf(cmax[1], __shfl_xor_sync(0xffffffffu, cmax[1], o));
        }
        float mn0 = fmaxf(m_run[0], cmax[0]);
        float mn1 = fmaxf(m_run[1], cmax[1]);
        float sc0 = __expf(m_run[0] - mn0);
        float sc1 = __expf(m_run[1] - mn1);
        m_run[0] = mn0; m_run[1] = mn1;

        float psum[2] = {0.f, 0.f};
#pragma unroll
        for (int nf = 0; nf < 8; nf++) {
            accS[nf][0] = __expf(accS[nf][0] - mn0);
            accS[nf][1] = __expf(accS[nf][1] - mn0);
            accS[nf][2] = __expf(accS[nf][2] - mn1);
            accS[nf][3] = __expf(accS[nf][3] - mn1);
            psum[0] += accS[nf][0] + accS[nf][1];
            psum[1] += accS[nf][2] + accS[nf][3];
        }
        l_t[0] = l_t[0] * sc0 + psum[0];
        l_t[1] = l_t[1] * sc1 + psum[1];

        if (t == 0) { sScale[jr] = sc0; sScale[jr + 8] = sc1; }
#pragma unroll
        for (int nf = 0; nf < 8; nf++) {
            int ic = nf * 8 + 2 * t;
            *(__half2*)&sP[jr * ST + ic]       = __floats2half2_rn(accS[nf][0], accS[nf][1]);
            *(__half2*)&sP[(jr + 8) * ST + ic] = __floats2half2_rn(accS[nf][2], accS[nf][3]);
        }
        __syncthreads();

        // ---- PV: O[32 c][32 j] per warp; rescale then accumulate ----
#pragma unroll
        for (int nf = 0; nf < 4; nf++) {
            float s0 = sScale[wj * 32 + nf * 8 + 2 * t];
            float s1 = sScale[wj * 32 + nf * 8 + 2 * t + 1];
#pragma unroll
            for (int mf = 0; mf < 2; mf++) {
                accO[mf][nf][0] *= s0; accO[mf][nf][1] *= s1;
                accO[mf][nf][2] *= s0; accO[mf][nf][3] *= s1;
            }
        }
#pragma unroll
        for (int ks = 0; ks < 4; ks++) {
            const int k0 = ks * 16;
            uint32_t af[2][4];
#pragma unroll
            for (int mf = 0; mf < 2; mf++) {
                int cr = wc * 32 + mf * 16 + g;
                af[mf][0] = *(const uint32_t*)&sV[cr * ST + k0 + 2 * t];
                af[mf][1] = *(const uint32_t*)&sV[(cr + 8) * ST + k0 + 2 * t];
                af[mf][2] = *(const uint32_t*)&sV[cr * ST + k0 + 2 * t + 8];
                af[mf][3] = *(const uint32_t*)&sV[(cr + 8) * ST + k0 + 2 * t + 8];
            }
#pragma unroll
            for (int nf = 0; nf < 4; nf++) {
                int jn = wj * 32 + nf * 8 + g;
                uint32_t b0 = *(const uint32_t*)&sP[jn * ST + k0 + 2 * t];
                uint32_t b1 = *(const uint32_t*)&sP[jn * ST + k0 + 2 * t + 8];
#pragma unroll
                for (int mf = 0; mf < 2; mf++)
                    MMA_F16(accO[mf][nf][0], accO[mf][nf][1], accO[mf][nf][2], accO[mf][nf][3],
                            af[mf][0], af[mf][1], af[mf][2], af[mf][3], b0, b1);
            }
        }
        __syncthreads();
    }

    // ---- finalize: 1/l per row, broadcast, write g_ocl ----
#pragma unroll
    for (int o = 1; o <= 2; o <<= 1) {
        l_t[0] += __shfl_xor_sync(0xffffffffu, l_t[0], o);
        l_t[1] += __shfl_xor_sync(0xffffffffu, l_t[1], o);
    }
    if (t == 0) {
        sScale[jr]     = 1.f / l_t[0];
        sScale[jr + 8] = 1.f / l_t[1];
    }
    __syncthreads();

    const int n = m >> 2, hh = m & 3;
    const int b = n / 9, rem = n % 9;
    const int wh = rem / 3, ww = rem % 3;
#pragma unroll
    for (int nf = 0; nf < 4; nf++) {
#pragma unroll
        for (int e = 0; e < 2; e++) {
            const int jl = wj * 32 + nf * 8 + 2 * t + e;
            const float inv = sScale[jl];
            const int j = jt * 128 + jl;
            const int h = wh * 32 + (j >> 5), w = ww * 32 + (j & 31);
            __half* dst = g_ocl + (((size_t)b * 98 + h + 1) * 98 + (w + 1)) * 256 + hh * 64;
#pragma unroll
            for (int mf = 0; mf < 2; mf++) {
                const int c0 = wc * 32 + mf * 16 + g;
                dst[c0]     = __float2half_rn(accO[mf][nf][0 + e] * inv);
                dst[c0 + 8] = __float2half_rn(accO[mf][nf][2 + e] * inv);
            }
        }
    }
}

// ===========================================================================
extern "C" void kernel_launch(void* const* d_in, const int* in_sizes, int n_in,
                              void* d_out, int out_size)
{
    (void)in_sizes; (void)n_in; (void)out_size;
    const float* x  = (const float*)d_in[0];
    const float* W1 = (const float*)d_in[1];
    const float* b1 = (const float*)d_in[2];
    const float* W2 = (const float*)d_in[3];
    const float* b2 = (const float*)d_in[4];
    float* out = (float*)d_out;

    const int CONV_SMEM = 2 * (128 + 256) * 40 * 2;   // 61440 B
    cudaFuncSetAttribute(conv_mma_kernel<512, 768, 0>,
                         cudaFuncAttributeMaxDynamicSharedMemorySize, CONV_SMEM);
    cudaFuncSetAttribute(conv_mma_kernel<256, 512, 1>,
                         cudaFuncAttributeMaxDynamicSharedMemorySize, CONV_SMEM);

    const int ATTN_SMEM = (128 + 64 + 64 + 128) * 72 * 2 + 128 * 4;  // 55808 B
    cudaFuncSetAttribute(fused_attn_kernel,
                         cudaFuncAttributeMaxDynamicSharedMemorySize, ATTN_SMEM);

    // pack inputs / weights (fp16)
    fill_border_kernel<512><<<(2 * 388 * 64 + 255) / 256, 256>>>();
    fill_border_kernel<256><<<(2 * 388 * 32 + 255) / 256, 256>>>();
    pack_cl_kernel<<<dim3(96, 16, 2), 256>>>(x);
    repack_w_kernel<768, 512, 0><<<(9 * 768 * 512 + 255) / 256, 256>>>(W1);
    repack_w_kernel<512, 256, 1><<<(9 * 512 * 256 + 255) / 256, 256>>>(W2);

    // conv1 + ReLU -> packed Q/K/V (fp16 mma)
    conv_mma_kernel<512, 768, 0><<<dim3(72, 6), 256, CONV_SMEM>>>(b1, nullptr, nullptr);

    // fused attention -> g_ocl (fp16 channels-last conv2 input)
    fused_attn_kernel<<<dim3(8, 72), 256, ATTN_SMEM>>>();

    // conv2 + residual (fp16 mma, fp32 epilogue)
    conv_mma_kernel<256, 512, 1><<<dim3(72, 4), 256, CONV_SMEM>>>(b2, x, out);
}

// round 7
// speedup vs baseline: 5.8017x; 1.0101x over previous
#include <cuda_runtime.h>
#include <cuda_fp16.h>
#include <math.h>
#include <stdint.h>

// ===========================================================================
// LocalAttention on sm_100 (portable PTX; tensor pipe via mma.sync f16.f32,
// fragments fed by ldmatrix):
//   conv3x3(512->768)+ReLU  -> fp16 m16n8k16 implicit GEMM, packs Q(*1/8)/K/V
//   fused flash-style windowed attention (fp16 operands, fp32 softmax/accum)
//   conv3x3(256->512)+residual -> fp16 m16n8k16 implicit GEMM (fp32 epilogue)
// ===========================================================================

// ------------------------------- scratch ----------------------------------
__device__ __half g_kt [72 * 1024 * 64];      // K: [m][i][c]
__device__ __half g_qt [72 * 1024 * 64];      // Q: [m][j][c] (pre-scaled 1/8)
__device__ __half g_v  [72 * 64 * 1024];      // V: [m][c][i]
__device__ __half g_xcl[2 * 98 * 98 * 512];   // padded channels-last input
__device__ __half g_ocl[2 * 98 * 98 * 256];   // padded channels-last attn out
__device__ __half g_w1p[9 * 768 * 512];       // W1 [s][co][ci]
__device__ __half g_w2p[9 * 512 * 256];       // W2 [s][co][ci]

// ------------------------------ helpers -----------------------------------
__device__ __forceinline__ uint32_t smem_u32(const void* p) {
    uint32_t a;
    asm("{ .reg .u64 t; cvta.to.shared.u64 t, %1; cvt.u32.u64 %0, t; }" : "=r"(a) : "l"(p));
    return a;
}

#define CP_ASYNC16(sm, gm) \
    asm volatile("cp.async.cg.shared.global [%0], [%1], 16;" :: "r"(sm), "l"(gm))
#define CP_COMMIT() asm volatile("cp.async.commit_group;" ::: "memory")
#define CP_WAIT1()  asm volatile("cp.async.wait_group 1;" ::: "memory")
#define CP_WAIT0()  asm volatile("cp.async.wait_group 0;" ::: "memory")

// fp16 mma, fp32 accum. C layout: c0=(g,2t) c1=(g,2t+1) c2=(g+8,2t) c3=(g+8,2t+1)
#define MMA_F16(c0,c1,c2,c3, a0,a1,a2,a3, b0,b1) \
    asm volatile("mma.sync.aligned.m16n8k16.row.col.f32.f16.f16.f32 " \
        "{%0,%1,%2,%3}, {%4,%5,%6,%7}, {%8,%9}, {%0,%1,%2,%3};" \
        : "+f"(c0), "+f"(c1), "+f"(c2), "+f"(c3) \
        : "r"(a0), "r"(a1), "r"(a2), "r"(a3), "r"(b0), "r"(b1))

// warp-collective 4x(8x8 b16) load; reg r_i <- matrix whose rows are supplied
// by threads 8i..8i+7
#define LDSM_X4(r0,r1,r2,r3, a) \
    asm volatile("ldmatrix.sync.aligned.m8n8.x4.shared.b16 {%0,%1,%2,%3}, [%4];" \
        : "=r"(r0), "=r"(r1), "=r"(r2), "=r"(r3) : "r"(a))

// ===========================================================================
// Pack kernels
// ===========================================================================
template <int C>
__global__ void fill_border_kernel() {
    __half* out = (C == 512) ? g_xcl : g_ocl;
    int idx = blockIdx.x * 256 + threadIdx.x;
    const int un = C / 8;                       // 16B units per pixel
    const int total = 2 * 388 * un;
    if (idx >= total) return;
    int u = idx % un;
    int cell = (idx / un) % 388;
    int b = idx / (388 * un);
    int h, w;
    if (cell < 98)        { h = 0;  w = cell; }
    else if (cell < 196)  { h = 97; w = cell - 98; }
    else if (cell < 292)  { h = cell - 196 + 1; w = 0; }
    else                  { h = cell - 292 + 1; w = 97; }
    uint4 z = make_uint4(0u, 0u, 0u, 0u);
    ((uint4*)&out[(((size_t)b * 98 + h) * 98 + w) * C])[u] = z;
}

__global__ __launch_bounds__(256) void pack_cl_kernel(const float* __restrict__ in) {
    __shared__ float s[32][97];
    const int h = blockIdx.x, cig = blockIdx.y, b = blockIdx.z;
    const int tid = threadIdx.x;
    for (int e = tid; e < 32 * 96; e += 256) {
        int ci = e / 96, w = e % 96;
        s[ci][w] = in[(((size_t)b * 512 + cig * 32 + ci) * 96 + h) * 96 + w];
    }
    __syncthreads();
    for (int e = tid; e < 96 * 32; e += 256) {
        int w = e >> 5, ci = e & 31;
        g_xcl[(((size_t)b * 98 + h + 1) * 98 + (w + 1)) * 512 + cig * 32 + ci] =
            __float2half_rn(s[ci][w]);
    }
}

template <int CO, int CI, int WHICH>
__global__ void repack_w_kernel(const float* __restrict__ W) {
    __half* Wp = (WHICH == 0) ? g_w1p : g_w2p;
    int idx = blockIdx.x * 256 + threadIdx.x;
    const int total = 9 * CO * CI;
    if (idx >= total) return;
    int s = idx / (CO * CI);
    int rem = idx % (CO * CI);
    int co = rem / CI, ci = rem % CI;
    Wp[idx] = __float2half_rn(W[((size_t)co * CI + ci) * 9 + s]);
}

// ===========================================================================
// fp16 mma.sync implicit-GEMM conv3x3 (ldmatrix fragment feed).
// CTA: D[128 co x 256 px]; 8 warps (2M x 4N), warp tile 64co x 64px.
// MODE 0: bias+ReLU -> fp16 Q(*0.125)/K [m][l][c] and V [m][c][l].
// MODE 1: bias+residual -> out (fp32 exact epilogue).
// ===========================================================================
template <int CIN, int COUT, int MODE>
__global__ void __launch_bounds__(256, 1)
conv_mma_kernel(const float* __restrict__ bias,
                const float* __restrict__ resid,
                float* __restrict__ out)
{
    constexpr int NIT  = 9 * CIN / 32;
    constexpr int AST  = 40;                 // halves per row
    constexpr int ABUF = 128 * AST;          // halves
    constexpr int BBUF = 256 * AST;
    constexpr int BUF  = ABUF + BBUF;

    const __half* __restrict__ Wp  = (MODE == 0) ? g_w1p : g_w2p;
    const __half* __restrict__ xcl = (MODE == 0) ? g_xcl : g_ocl;
    const int XC = (MODE == 0) ? 512 : 256;

    extern __shared__ __half smh[];
    const uint32_t sb = smem_u32(smh);

    const int tid  = threadIdx.x;
    const int wid  = tid >> 5;
    const int lane = tid & 31;
    const int g = lane >> 2;
    const int t = lane & 3;
    const int wm = wid >> 2;              // 0..1 : co 64-half
    const int wn = wid & 3;               // 0..3 : px 64-quarter
    const uint32_t quad = lane >> 3, rin = lane & 7;

    // per-lane ldmatrix byte offsets (within a 16x16 / 16x(2x8) tile)
    const uint32_t a_lane = (((quad & 1) * 8 + rin) * AST + (quad >> 1) * 8) * 2;
    const uint32_t b_lane = (((quad >> 1) * 8 + rin) * AST + (quad & 1) * 8) * 2;

    const int pt = blockIdx.x;            // 72 = b(2) x 12 rowbands x 3 colbands
    const int b  = pt / 36;
    const int r  = pt % 36;
    const int h0 = (r / 3) * 8;
    const int w0 = (r % 3) * 32;
    const int co0 = blockIdx.y * 128;

    const int arow  = tid >> 1;                 // A: 2 threads per 64B row
    const int ahalf = (tid & 1) * 32;           // byte offset within row
    const int bpr = tid >> 5, bpc = tid & 31;   // B: 1 thread per 64B row

    auto load_stage = [&](int it, int buf) {
        const int s   = it / (CIN / 32);
        const int ci0 = (it % (CIN / 32)) * 32;
        const int kh = s / 3, kw = s % 3;
        const uint32_t abase = sb + (buf * BUF + arow * AST) * 2 + ahalf;
        const char* ga = (const char*)(Wp + ((size_t)s * COUT + co0 + arow) * CIN + ci0) + ahalf;
        CP_ASYNC16(abase, ga);
        CP_ASYNC16(abase + 16, ga + 16);
        const uint32_t bbase = sb + (buf * BUF + ABUF + tid * AST) * 2;
        const char* gb = (const char*)
            (xcl + (((size_t)(b * 98 + h0 + bpr + kh)) * 98 + (w0 + bpc + kw)) * XC + ci0);
#pragma unroll
        for (int i = 0; i < 4; i++) CP_ASYNC16(bbase + i * 16, gb + i * 16);
        CP_COMMIT();
    };

    float acc[4][8][4];
#pragma unroll
    for (int mf = 0; mf < 4; mf++)
#pragma unroll
        for (int nf = 0; nf < 8; nf++)
#pragma unroll
            for (int e = 0; e < 4; e++) acc[mf][nf][e] = 0.f;

    load_stage(0, 0);

    for (int it = 0; it < NIT; ++it) {
        const int buf = it & 1;
        if (it + 1 < NIT) { load_stage(it + 1, buf ^ 1); CP_WAIT1(); }
        else              { CP_WAIT0(); }
        __syncthreads();

        const uint32_t a_base = sb + (buf * BUF + wm * 64 * AST) * 2 + a_lane;
        const uint32_t b_base = sb + (buf * BUF + ABUF + wn * 64 * AST) * 2 + b_lane;
#pragma unroll
        for (int ks = 0; ks < 2; ks++) {
            const uint32_t kofs = ks * 32;          // 16 halves
            uint32_t bf[4][4];
#pragma unroll
            for (int pf = 0; pf < 4; pf++)
                LDSM_X4(bf[pf][0], bf[pf][1], bf[pf][2], bf[pf][3],
                        b_base + pf * 16 * AST * 2 + kofs);
#pragma unroll
            for (int mf = 0; mf < 4; mf++) {
                uint32_t a0, a1, a2, a3;
                LDSM_X4(a0, a1, a2, a3, a_base + mf * 16 * AST * 2 + kofs);
#pragma unroll
                for (int pf = 0; pf < 4; pf++) {
                    MMA_F16(acc[mf][2*pf][0], acc[mf][2*pf][1], acc[mf][2*pf][2], acc[mf][2*pf][3],
                            a0, a1, a2, a3, bf[pf][0], bf[pf][1]);
                    MMA_F16(acc[mf][2*pf+1][0], acc[mf][2*pf+1][1], acc[mf][2*pf+1][2], acc[mf][2*pf+1][3],
                            a0, a1, a2, a3, bf[pf][2], bf[pf][3]);
                }
            }
        }
        __syncthreads();
    }

    // ----------------------------- epilogue -------------------------------
#pragma unroll
    for (int mf = 0; mf < 4; mf++) {
#pragma unroll
        for (int half8 = 0; half8 < 2; half8++) {
            const int co_g = co0 + wm * 64 + mf * 16 + g + half8 * 8;
            const float bv = __ldg(&bias[co_g]);
            if (MODE == 0) {
                const int part = co_g >> 8;          // 0=K 1=V 2=Q
                const int hh   = (co_g >> 6) & 3;
                const int cc   = co_g & 63;
                const int mm   = ((b * 9 + (h0 >> 5) * 3 + (w0 >> 5)) << 2) + hh;
                const float qs = (part == 2) ? 0.125f : 1.0f;
#pragma unroll
                for (int nf = 0; nf < 8; nf++) {
                    const int px0 = wn * 64 + nf * 8 + 2 * t;
                    float v0 = qs * fmaxf(acc[mf][nf][half8 * 2 + 0] + bv, 0.f);
                    float v1 = qs * fmaxf(acc[mf][nf][half8 * 2 + 1] + bv, 0.f);
                    const int l0 = ((h0 & 31) + (px0 >> 5)) * 32 + (px0 & 31);
                    if (part == 1) {
                        __half2* dst = (__half2*)(g_v + ((size_t)(mm * 64 + cc)) * 1024 + l0);
                        *dst = __floats2half2_rn(v0, v1);
                    } else {
                        __half* dq = (part ? g_qt : g_kt) + ((size_t)mm * 1024 + l0) * 64 + cc;
                        dq[0]  = __float2half_rn(v0);
                        dq[64] = __float2half_rn(v1);
                    }
                }
            } else {
#pragma unroll
                for (int nf = 0; nf < 8; nf++) {
                    const int px0 = wn * 64 + nf * 8 + 2 * t;
                    const int h = h0 + (px0 >> 5), w = w0 + (px0 & 31);
                    const size_t idx = (((size_t)(b * 512 + co_g) * 96) + h) * 96 + w;
                    float2 rv = *(const float2*)(resid + idx);
                    float2 v;
                    v.x = rv.x + bv + acc[mf][nf][half8 * 2 + 0];
                    v.y = rv.y + bv + acc[mf][nf][half8 * 2 + 1];
                    *(float2*)(out + idx) = v;
                }
            }
        }
    }
}

// ===========================================================================
// Fused flash-style attention, fp16 operands + ldmatrix. CTA = (m, 128-j).
// 256 threads, 8 warps; K/V in 64-i chunks (16 chunks); smem ~55KB -> occ 2.
//   QK: warp = 16 j x 64 i ;  PV: warp = 32 c x 32 j
// Q pre-scaled by 1/8, fragments hoisted. Writes g_ocl (fp16 CL).
// ===========================================================================
__global__ void __launch_bounds__(256, 2) fused_attn_kernel()
{
    constexpr int ST = 72;                 // halves per row (pad 64 -> 72)
    extern __shared__ __half sh[];
    __half* sQ = sh;                       // [128][72]
    __half* sK = sQ + 128 * ST;            // [64][72]
    __half* sV = sK + 64 * ST;             // [64][72]
    __half* sP = sV + 64 * ST;             // [128][72]  (P[j][i])
    float* sScale = (float*)(sP + 128 * ST);   // [128]

    const int m  = blockIdx.y;
    const int jt = blockIdx.x;            // 0..7
    const int tid = threadIdx.x, wid = tid >> 5, lane = tid & 31;
    const int g = lane >> 2, t = lane & 3;
    const int wc = wid >> 2;              // PV c-half (0..1)
    const int wj = wid & 3;               // PV j-quarter (0..3)
    const uint32_t quad = lane >> 3, rin = lane & 7;
    const uint32_t a_lane = (((quad & 1) * 8 + rin) * ST + (quad >> 1) * 8) * 2;
    const uint32_t b_lane = (((quad >> 1) * 8 + rin) * ST + (quad & 1) * 8) * 2;

    const uint32_t sqb = smem_u32(sQ), skb = smem_u32(sK);
    const uint32_t svb = smem_u32(sV), spb = smem_u32(sP);

    // ---- load Q tile [128 j][64 c] halves, then hoist fragments ----
    {
        const char* Qg = (const char*)(g_qt + ((size_t)m * 1024 + jt * 128) * 64);
        for (int e = tid; e < 1024; e += 256) {
            int r = e >> 3, u = e & 7;
            CP_ASYNC16(sqb + (r * ST) * 2 + u * 16, Qg + r * 128 + u * 16);
        }
        CP_COMMIT();
        CP_WAIT0();
        __syncthreads();
    }
    uint32_t qf[4][4];
    {
        const uint32_t qa = sqb + (wid * 16 * ST) * 2 + a_lane;
#pragma unroll
        for (int ks = 0; ks < 4; ks++)
            LDSM_X4(qf[ks][0], qf[ks][1], qf[ks][2], qf[ks][3], qa + ks * 32);
    }

    float accO[2][4][4];
#pragma unroll
    for (int mf = 0; mf < 2; mf++)
#pragma unroll
        for (int nf = 0; nf < 4; nf++)
#pragma unroll
            for (int e = 0; e < 4; e++) accO[mf][nf][e] = 0.f;

    float m_run[2] = {-1e30f, -1e30f};
    float l_t[2]   = {0.f, 0.f};
    const int jr = wid * 16 + g;          // QK row (and +8)

    for (int ch = 0; ch < 16; ch++) {
        const int i0 = ch * 64;
        // ---- load K chunk [64 i][64 c], V chunk [64 c][64 i] (halves) ----
        const char* Kg = (const char*)(g_kt + ((size_t)m * 1024 + i0) * 64);
        const char* Vg = (const char*)(g_v + (size_t)m * 64 * 1024 + i0);
        for (int e = tid; e < 512; e += 256) {
            int r = e >> 3, u = e & 7;
            CP_ASYNC16(skb + (r * ST) * 2 + u * 16, Kg + r * 128 + u * 16);
        }
        for (int e = tid; e < 512; e += 256) {
            int r = e >> 3, u = e & 7;
            CP_ASYNC16(svb + (r * ST) * 2 + u * 16, Vg + r * 2048 + u * 16);
        }
        CP_COMMIT();
        CP_WAIT0();
        __syncthreads();

        // ---- QK: S[16 j][64 i] per warp (k = c = 64, 4 k-steps) ----
        float accS[8][4];
#pragma unroll
        for (int nf = 0; nf < 8; nf++)
#pragma unroll
            for (int e = 0; e < 4; e++) accS[nf][e] = 0.f;

        const uint32_t kb = skb + b_lane;
#pragma unroll
        for (int ks = 0; ks < 4; ks++) {
            const uint32_t kofs = ks * 32;
#pragma unroll
            for (int pf = 0; pf < 4; pf++) {
                uint32_t b0, b1, b2, b3;
                LDSM_X4(b0, b1, b2, b3, kb + pf * 16 * ST * 2 + kofs);
                MMA_F16(accS[2*pf][0], accS[2*pf][1], accS[2*pf][2], accS[2*pf][3],
                        qf[ks][0], qf[ks][1], qf[ks][2], qf[ks][3], b0, b1);
                MMA_F16(accS[2*pf+1][0], accS[2*pf+1][1], accS[2*pf+1][2], accS[2*pf+1][3],
                        qf[ks][0], qf[ks][1], qf[ks][2], qf[ks][3], b2, b3);
            }
        }

        // ---- online softmax over i (cols), rows jr / jr+8 ----
        float cmax[2] = {-1e30f, -1e30f};
#pragma unroll
        for (int nf = 0; nf < 8; nf++) {
            cmax[0] = fmaxf(cmax[0], fmaxf(accS[nf][0], accS[nf][1]));
            cmax[1] = fmaxf(cmax[1], fmaxf(accS[nf][2], accS[nf][3]));
        }
#pragma unroll
        for (int o = 1; o <= 2; o <<= 1) {
            cmax[0] = fmaxf(cmax[0], __shfl_xor_sync(0xffffffffu, cmax[0], o));
            cmax[1] = fmaxf(cmax[1], __shfl_xor_sync(0xffffffffu, cmax[1], o));
        }
        float mn0 = fmaxf(m_run[0], cmax[0]);
        float mn1 = fmaxf(m_run[1], cmax[1]);
        float sc0 = __expf(m_run[0] - mn0);
        float sc1 = __expf(m_run[1] - mn1);
        m_run[0] = mn0; m_run[1] = mn1;

        float psum[2] = {0.f, 0.f};
#pragma unroll
        for (int nf = 0; nf < 8; nf++) {
            accS[nf][0] = __expf(accS[nf][0] - mn0);
            accS[nf][1] = __expf(accS[nf][1] - mn0);
            accS[nf][2] = __expf(accS[nf][2] - mn1);
            accS[nf][3] = __expf(accS[nf][3] - mn1);
            psum[0] += accS[nf][0] + accS[nf][1];
            psum[1] += accS[nf][2] + accS[nf][3];
        }
        l_t[0] = l_t[0] * sc0 + psum[0];
        l_t[1] = l_t[1] * sc1 + psum[1];

        if (t == 0) { sScale[jr] = sc0; sScale[jr + 8] = sc1; }
#pragma unroll
        for (int nf = 0; nf < 8; nf++) {
            int ic = nf * 8 + 2 * t;
            *(__half2*)&sP[jr * ST + ic]       = __floats2half2_rn(accS[nf][0], accS[nf][1]);
            *(__half2*)&sP[(jr + 8) * ST + ic] = __floats2half2_rn(accS[nf][2], accS[nf][3]);
        }
        __syncthreads();

        // ---- PV: O[32 c][32 j] per warp; rescale then accumulate ----
#pragma unroll
        for (int nf = 0; nf < 4; nf++) {
            float s0 = sScale[wj * 32 + nf * 8 + 2 * t];
            float s1 = sScale[wj * 32 + nf * 8 + 2 * t + 1];
#pragma unroll
            for (int mf = 0; mf < 2; mf++) {
                accO[mf][nf][0] *= s0; accO[mf][nf][1] *= s1;
                accO[mf][nf][2] *= s0; accO[mf][nf][3] *= s1;
            }
        }
        const uint32_t va = svb + (wc * 32 * ST) * 2 + a_lane;
        const uint32_t pb = spb + (wj * 32 * ST) * 2 + b_lane;
#pragma unroll
        for (int ks = 0; ks < 4; ks++) {
            const uint32_t kofs = ks * 32;
            uint32_t af[2][4];
#pragma unroll
            for (int mf = 0; mf < 2; mf++)
                LDSM_X4(af[mf][0], af[mf][1], af[mf][2], af[mf][3],
                        va + mf * 16 * ST * 2 + kofs);
#pragma unroll
            for (int pf = 0; pf < 2; pf++) {
                uint32_t b0, b1, b2, b3;
                LDSM_X4(b0, b1, b2, b3, pb + pf * 16 * ST * 2 + kofs);
#pragma unroll
                for (int mf = 0; mf < 2; mf++) {
                    MMA_F16(accO[mf][2*pf][0], accO[mf][2*pf][1], accO[mf][2*pf][2], accO[mf][2*pf][3],
                            af[mf][0], af[mf][1], af[mf][2], af[mf][3], b0, b1);
                    MMA_F16(accO[mf][2*pf+1][0], accO[mf][2*pf+1][1], accO[mf][2*pf+1][2], accO[mf][2*pf+1][3],
                            af[mf][0], af[mf][1], af[mf][2], af[mf][3], b2, b3);
                }
            }
        }
        __syncthreads();
    }

    // ---- finalize: 1/l per row, broadcast, write g_ocl ----
#pragma unroll
    for (int o = 1; o <= 2; o <<= 1) {
        l_t[0] += __shfl_xor_sync(0xffffffffu, l_t[0], o);
        l_t[1] += __shfl_xor_sync(0xffffffffu, l_t[1], o);
    }
    if (t == 0) {
        sScale[jr]     = 1.f / l_t[0];
        sScale[jr + 8] = 1.f / l_t[1];
    }
    __syncthreads();

    const int n = m >> 2, hh = m & 3;
    const int b = n / 9, rem = n % 9;
    const int wh = rem / 3, ww = rem % 3;
#pragma unroll
    for (int nf = 0; nf < 4; nf++) {
#pragma unroll
        for (int e = 0; e < 2; e++) {
            const int jl = wj * 32 + nf * 8 + 2 * t + e;
            const float inv = sScale[jl];
            const int j = jt * 128 + jl;
            const int h = wh * 32 + (j >> 5), w = ww * 32 + (j & 31);
            __half* dst = g_ocl + (((size_t)b * 98 + h + 1) * 98 + (w + 1)) * 256 + hh * 64;
#pragma unroll
            for (int mf = 0; mf < 2; mf++) {
                const int c0 = wc * 32 + mf * 16 + g;
                dst[c0]     = __float2half_rn(accO[mf][nf][0 + e] * inv);
                dst[c0 + 8] = __float2half_rn(accO[mf][nf][2 + e] * inv);
            }
        }
    }
}

// ===========================================================================
extern "C" void kernel_launch(void* const* d_in, const int* in_sizes, int n_in,
                              void* d_out, int out_size)
{
    (void)in_sizes; (void)n_in; (void)out_size;
    const float* x  = (const float*)d_in[0];
    const float* W1 = (const float*)d_in[1];
    const float* b1 = (const float*)d_in[2];
    const float* W2 = (const float*)d_in[3];
    const float* b2 = (const float*)d_in[4];
    float* out = (float*)d_out;

    const int CONV_SMEM = 2 * (128 + 256) * 40 * 2;   // 61440 B
    cudaFuncSetAttribute(conv_mma_kernel<512, 768, 0>,
                         cudaFuncAttributeMaxDynamicSharedMemorySize, CONV_SMEM);
    cudaFuncSetAttribute(conv_mma_kernel<256, 512, 1>,
                         cudaFuncAttributeMaxDynamicSharedMemorySize, CONV_SMEM);

    const int ATTN_SMEM = (128 + 64 + 64 + 128) * 72 * 2 + 128 * 4;  // 55808 B
    cudaFuncSetAttribute(fused_attn_kernel,
                         cudaFuncAttributeMaxDynamicSharedMemorySize, ATTN_SMEM);

    // pack inputs / weights (fp16)
    fill_border_kernel<512><<<(2 * 388 * 64 + 255) / 256, 256>>>();
    fill_border_kernel<256><<<(2 * 388 * 32 + 255) / 256, 256>>>();
    pack_cl_kernel<<<dim3(96, 16, 2), 256>>>(x);
    repack_w_kernel<768, 512, 0><<<(9 * 768 * 512 + 255) / 256, 256>>>(W1);
    repack_w_kernel<512, 256, 1><<<(9 * 512 * 256 + 255) / 256, 256>>>(W2);

    // conv1 + ReLU -> packed Q/K/V (fp16 mma)
    conv_mma_kernel<512, 768, 0><<<dim3(72, 6), 256, CONV_SMEM>>>(b1, nullptr, nullptr);

    // fused attention -> g_ocl (fp16 channels-last conv2 input)
    fused_attn_kernel<<<dim3(8, 72), 256, ATTN_SMEM>>>();

    // conv2 + residual (fp16 mma, fp32 epilogue)
    conv_mma_kernel<256, 512, 1><<<dim3(72, 4), 256, CONV_SMEM>>>(b2, x, out);
}

// round 9
// speedup vs baseline: 10.1487x; 1.7493x over previous
#include <cuda_runtime.h>
#include <cuda_fp16.h>
#include <math.h>
#include <stdint.h>

// ===========================================================================
// LocalAttention on sm_100 (portable PTX; mma.sync f16.f32 + ldmatrix):
//   conv3x3(512->768)+ReLU  -> halo-resident fp16 implicit GEMM, packs Q/K/V
//   fused flash-style windowed attention (fp16 operands, fp32 softmax/accum)
//   conv3x3(256->512)+residual -> halo-resident fp16 implicit GEMM
// Conv inner loop keeps a 10x34-pixel input halo resident in smem and runs
// all 9 filter taps against it (B traffic /9, syncs /9).
// ===========================================================================

// ------------------------------- scratch ----------------------------------
__device__ __half g_kt [72 * 1024 * 64];      // K: [m][i][c]
__device__ __half g_qt [72 * 1024 * 64];      // Q: [m][j][c] (pre-scaled 1/8)
__device__ __half g_v  [72 * 64 * 1024];      // V: [m][c][i]
__device__ __half g_xcl[2 * 98 * 98 * 512];   // padded channels-last input
__device__ __half g_ocl[2 * 98 * 98 * 256];   // padded channels-last attn out
__device__ __half g_w1p[9 * 768 * 512];       // W1 [s][co][ci]
__device__ __half g_w2p[9 * 512 * 256];       // W2 [s][co][ci]

// ------------------------------ helpers -----------------------------------
__device__ __forceinline__ uint32_t smem_u32(const void* p) {
    uint32_t a;
    asm("{ .reg .u64 t; cvta.to.shared.u64 t, %1; cvt.u32.u64 %0, t; }" : "=r"(a) : "l"(p));
    return a;
}

#define CP_ASYNC16(sm, gm) \
    asm volatile("cp.async.cg.shared.global [%0], [%1], 16;" :: "r"(sm), "l"(gm))
#define CP_COMMIT() asm volatile("cp.async.commit_group;" ::: "memory")
#define CP_WAIT1()  asm volatile("cp.async.wait_group 1;" ::: "memory")
#define CP_WAIT0()  asm volatile("cp.async.wait_group 0;" ::: "memory")

#define MMA_F16(c0,c1,c2,c3, a0,a1,a2,a3, b0,b1) \
    asm volatile("mma.sync.aligned.m16n8k16.row.col.f32.f16.f16.f32 " \
        "{%0,%1,%2,%3}, {%4,%5,%6,%7}, {%8,%9}, {%0,%1,%2,%3};" \
        : "+f"(c0), "+f"(c1), "+f"(c2), "+f"(c3) \
        : "r"(a0), "r"(a1), "r"(a2), "r"(a3), "r"(b0), "r"(b1))

#define LDSM_X4(r0,r1,r2,r3, a) \
    asm volatile("ldmatrix.sync.aligned.m8n8.x4.shared.b16 {%0,%1,%2,%3}, [%4];" \
        : "=r"(r0), "=r"(r1), "=r"(r2), "=r"(r3) : "r"(a))

// 64B rows (32 halves), 16B-unit XOR swizzle: conflict-free for ldmatrix
__device__ __forceinline__ uint32_t swz_addr(uint32_t base, int row, int seg) {
    return base + row * 64 + ((seg ^ ((row >> 1) & 3)) << 4);
}

// ===========================================================================
// Pack kernels
// ===========================================================================
template <int C>
__global__ void fill_border_kernel() {
    __half* out = (C == 512) ? g_xcl : g_ocl;
    int idx = blockIdx.x * 256 + threadIdx.x;
    const int un = C / 8;
    const int total = 2 * 388 * un;
    if (idx >= total) return;
    int u = idx % un;
    int cell = (idx / un) % 388;
    int b = idx / (388 * un);
    int h, w;
    if (cell < 98)        { h = 0;  w = cell; }
    else if (cell < 196)  { h = 97; w = cell - 98; }
    else if (cell < 292)  { h = cell - 196 + 1; w = 0; }
    else                  { h = cell - 292 + 1; w = 97; }
    uint4 z = make_uint4(0u, 0u, 0u, 0u);
    ((uint4*)&out[(((size_t)b * 98 + h) * 98 + w) * C])[u] = z;
}

__global__ __launch_bounds__(256) void pack_cl_kernel(const float* __restrict__ in) {
    __shared__ float s[32][97];
    const int h = blockIdx.x, cig = blockIdx.y, b = blockIdx.z;
    const int tid = threadIdx.x;
    for (int e = tid; e < 32 * 96; e += 256) {
        int ci = e / 96, w = e % 96;
        s[ci][w] = in[(((size_t)b * 512 + cig * 32 + ci) * 96 + h) * 96 + w];
    }
    __syncthreads();
    for (int e = tid; e < 96 * 32; e += 256) {
        int w = e >> 5, ci = e & 31;
        g_xcl[(((size_t)b * 98 + h + 1) * 98 + (w + 1)) * 512 + cig * 32 + ci] =
            __float2half_rn(s[ci][w]);
    }
}

template <int CO, int CI, int WHICH>
__global__ void repack_w_kernel(const float* __restrict__ W) {
    __half* Wp = (WHICH == 0) ? g_w1p : g_w2p;
    int idx = blockIdx.x * 256 + threadIdx.x;
    const int total = 9 * CO * CI;
    if (idx >= total) return;
    int s = idx / (CO * CI);
    int rem = idx % (CO * CI);
    int co = rem / CI, ci = rem % CI;
    Wp[idx] = __float2half_rn(W[((size_t)co * CI + ci) * 9 + s]);
}

// ===========================================================================
// Halo-resident fp16 implicit-GEMM conv3x3.
// CTA: D[128 co x 256 px(8x32)]; 8 warps (2M x 4N), warp tile 64co x 64px.
// Per 32-ci chunk: smem holds A[9][128][32] (all taps) + halo B[340][32]
// (10x34 pixels); MMA sweeps all 9 taps against the resident halo.
// MODE 0: bias+ReLU -> fp16 Q(*0.125)/K [m][l][c] and V [m][c][l].
// MODE 1: bias+residual -> out (fp32 exact epilogue).
// ===========================================================================
template <int CIN, int COUT, int MODE>
__global__ void __launch_bounds__(256, 1)
conv_mma_kernel(const float* __restrict__ bias,
                const float* __restrict__ resid,
                float* __restrict__ out)
{
    constexpr int NCH   = CIN / 32;          // ci chunks
    constexpr int ABYT  = 9 * 128 * 64;      // 73728 B per buffer
    constexpr int BBYT  = 340 * 64;          // 21760 B per buffer
    constexpr int BUFB  = ABYT + BBYT;       // 95488 B

    const __half* __restrict__ Wp  = (MODE == 0) ? g_w1p : g_w2p;
    const __half* __restrict__ xcl = (MODE == 0) ? g_xcl : g_ocl;
    const int XC = (MODE == 0) ? 512 : 256;

    extern __shared__ __half smh[];
    const uint32_t sb = smem_u32(smh);

    const int tid  = threadIdx.x;
    const int wid  = tid >> 5;
    const int lane = tid & 31;
    const int g = lane >> 2;
    const int t = lane & 3;
    const int wm = wid >> 2;              // 0..1 : co 64-half
    const int wn = wid & 3;               // 0..3 : px 64-quarter
    const int quad = lane >> 3, rin = lane & 7;

    const int a_rin = (quad & 1) * 8 + rin;   // A row within 16, seg-half quad>>1
    const int a_sb  = quad >> 1;
    const int b_rin = (quad >> 1) * 8 + rin;  // B row within 16, seg-half quad&1
    const int b_sb  = quad & 1;

    const int pt = blockIdx.x;            // 72 = b(2) x 12 rowbands x 3 colbands
    const int b  = pt / 36;
    const int r  = pt % 36;
    const int h0 = (r / 3) * 8;
    const int w0 = (r % 3) * 32;
    const int co0 = blockIdx.y * 128;

    // halo-row offset of warp's pf-th 16-px block (pf 0..3)
    int pxc[4];
#pragma unroll
    for (int pf = 0; pf < 4; pf++) {
        int n0 = wn * 64 + pf * 16;
        pxc[pf] = (n0 >> 5) * 34 + (n0 & 31);
    }

    auto load_stage = [&](int ch, int buf) {
        const int ci0 = ch * 32;
        const uint32_t base = sb + buf * BUFB;
        // A: 9 taps x 128 co x 64B rows -> 4608 cp16
#pragma unroll
        for (int i = 0; i < 18; i++) {
            int e = tid + i * 256;
            int row = e >> 2, seg = e & 3;
            int s = row >> 7, cor = row & 127;
            const char* ga = (const char*)
                (Wp + ((size_t)s * COUT + co0 + cor) * CIN + ci0) + seg * 16;
            CP_ASYNC16(swz_addr(base, row, seg), ga);
        }
        // B halo: 340 pixel rows x 64B -> 1360 cp16
#pragma unroll
        for (int i = 0; i < 6; i++) {
            int e = tid + i * 256;
            if (e < 1360) {
                int row = e >> 2, seg = e & 3;
                int hr = row / 34, wc = row % 34;
                const char* gb = (const char*)
                    (xcl + (((size_t)(b * 98 + h0 + hr)) * 98 + (w0 + wc)) * XC + ci0) + seg * 16;
                CP_ASYNC16(swz_addr(base + ABYT, row, seg), gb);
            }
        }
        CP_COMMIT();
    };

    float acc[4][8][4];
#pragma unroll
    for (int mf = 0; mf < 4; mf++)
#pragma unroll
        for (int nf = 0; nf < 8; nf++)
#pragma unroll
            for (int e = 0; e < 4; e++) acc[mf][nf][e] = 0.f;

    load_stage(0, 0);

    for (int ch = 0; ch < NCH; ++ch) {
        const int buf = ch & 1;
        if (ch + 1 < NCH) { load_stage(ch + 1, buf ^ 1); CP_WAIT1(); }
        else              { CP_WAIT0(); }
        __syncthreads();

        const uint32_t abase = sb + buf * BUFB;
        const uint32_t bbase = abase + ABYT;
        const int arow0 = wm * 64 + a_rin;

#pragma unroll 1
        for (int s = 0; s < 9; s++) {
            const int kh = s / 3, kw = s % 3;
            const int hb = kh * 34 + kw + b_rin;      // halo row base for B frags
            const int ab = s * 128 + arow0;           // A row base for this tap
#pragma unroll
            for (int ks = 0; ks < 2; ks++) {
                const int bseg = ks * 2 + b_sb;
                const int aseg = ks * 2 + a_sb;
                uint32_t bf[4][4];
#pragma unroll
                for (int pf = 0; pf < 4; pf++) {
                    int hrow = hb + pxc[pf];
                    LDSM_X4(bf[pf][0], bf[pf][1], bf[pf][2], bf[pf][3],
                            swz_addr(bbase, hrow, bseg));
                }
#pragma unroll
                for (int mf = 0; mf < 4; mf++) {
                    uint32_t a0, a1, a2, a3;
                    LDSM_X4(a0, a1, a2, a3, swz_addr(abase, ab + mf * 16, aseg));
#pragma unroll
                    for (int pf = 0; pf < 4; pf++) {
                        MMA_F16(acc[mf][2*pf][0], acc[mf][2*pf][1], acc[mf][2*pf][2], acc[mf][2*pf][3],
                                a0, a1, a2, a3, bf[pf][0], bf[pf][1]);
                        MMA_F16(acc[mf][2*pf+1][0], acc[mf][2*pf+1][1], acc[mf][2*pf+1][2], acc[mf][2*pf+1][3],
                                a0, a1, a2, a3, bf[pf][2], bf[pf][3]);
                    }
                }
            }
        }
        __syncthreads();
    }

    // ----------------------------- epilogue -------------------------------
#pragma unroll
    for (int mf = 0; mf < 4; mf++) {
#pragma unroll
        for (int half8 = 0; half8 < 2; half8++) {
            const int co_g = co0 + wm * 64 + mf * 16 + g + half8 * 8;
            const float bv = __ldg(&bias[co_g]);
            if (MODE == 0) {
                const int part = co_g >> 8;          // 0=K 1=V 2=Q
                const int hh   = (co_g >> 6) & 3;
                const int cc   = co_g & 63;
                const int mm   = ((b * 9 + (h0 >> 5) * 3 + (w0 >> 5)) << 2) + hh;
                const float qs = (part == 2) ? 0.125f : 1.0f;
#pragma unroll
                for (int nf = 0; nf < 8; nf++) {
                    const int px0 = wn * 64 + nf * 8 + 2 * t;
                    float v0 = qs * fmaxf(acc[mf][nf][half8 * 2 + 0] + bv, 0.f);
                    float v1 = qs * fmaxf(acc[mf][nf][half8 * 2 + 1] + bv, 0.f);
                    const int l0 = ((h0 & 31) + (px0 >> 5)) * 32 + (px0 & 31);
                    if (part == 1) {
                        __half2* dst = (__half2*)(g_v + ((size_t)(mm * 64 + cc)) * 1024 + l0);
                        *dst = __floats2half2_rn(v0, v1);
                    } else {
                        __half* dq = (part ? g_qt : g_kt) + ((size_t)mm * 1024 + l0) * 64 + cc;
                        dq[0]  = __float2half_rn(v0);
                        dq[64] = __float2half_rn(v1);
                    }
                }
            } else {
#pragma unroll
                for (int nf = 0; nf < 8; nf++) {
                    const int px0 = wn * 64 + nf * 8 + 2 * t;
                    const int h = h0 + (px0 >> 5), w = w0 + (px0 & 31);
                    const size_t idx = (((size_t)(b * 512 + co_g) * 96) + h) * 96 + w;
                    float2 rv = *(const float2*)(resid + idx);
                    float2 v;
                    v.x = rv.x + bv + acc[mf][nf][half8 * 2 + 0];
                    v.y = rv.y + bv + acc[mf][nf][half8 * 2 + 1];
                    *(float2*)(out + idx) = v;
                }
            }
        }
    }
}

// ===========================================================================
// Fused flash-style attention, fp16 operands + ldmatrix (unchanged from R7).
// ===========================================================================
__global__ void __launch_bounds__(256, 2) fused_attn_kernel()
{
    constexpr int ST = 72;
    extern __shared__ __half sh[];
    __half* sQ = sh;                       // [128][72]
    __half* sK = sQ + 128 * ST;            // [64][72]
    __half* sV = sK + 64 * ST;             // [64][72]
    __half* sP = sV + 64 * ST;             // [128][72]
    float* sScale = (float*)(sP + 128 * ST);

    const int m  = blockIdx.y;
    const int jt = blockIdx.x;
    const int tid = threadIdx.x, wid = tid >> 5, lane = tid & 31;
    const int g = lane >> 2, t = lane & 3;
    const int wc = wid >> 2;
    const int wj = wid & 3;
    const uint32_t quad = lane >> 3, rin = lane & 7;
    const uint32_t a_lane = (((quad & 1) * 8 + rin) * ST + (quad >> 1) * 8) * 2;
    const uint32_t b_lane = (((quad >> 1) * 8 + rin) * ST + (quad & 1) * 8) * 2;

    const uint32_t sqb = smem_u32(sQ), skb = smem_u32(sK);
    const uint32_t svb = smem_u32(sV), spb = smem_u32(sP);

    {
        const char* Qg = (const char*)(g_qt + ((size_t)m * 1024 + jt * 128) * 64);
        for (int e = tid; e < 1024; e += 256) {
            int r = e >> 3, u = e & 7;
            CP_ASYNC16(sqb + (r * ST) * 2 + u * 16, Qg + r * 128 + u * 16);
        }
        CP_COMMIT();
        CP_WAIT0();
        __syncthreads();
    }
    uint32_t qf[4][4];
    {
        const uint32_t qa = sqb + (wid * 16 * ST) * 2 + a_lane;
#pragma unroll
        for (int ks = 0; ks < 4; ks++)
            LDSM_X4(qf[ks][0], qf[ks][1], qf[ks][2], qf[ks][3], qa + ks * 32);
    }

    float accO[2][4][4];
#pragma unroll
    for (int mf = 0; mf < 2; mf++)
#pragma unroll
        for (int nf = 0; nf < 4; nf++)
#pragma unroll
            for (int e = 0; e < 4; e++) accO[mf][nf][e] = 0.f;

    float m_run[2] = {-1e30f, -1e30f};
    float l_t[2]   = {0.f, 0.f};
    const int jr = wid * 16 + g;

    for (int ch = 0; ch < 16; ch++) {
        const int i0 = ch * 64;
        const char* Kg = (const char*)(g_kt + ((size_t)m * 1024 + i0) * 64);
        const char* Vg = (const char*)(g_v + (size_t)m * 64 * 1024 + i0);
        for (int e = tid; e < 512; e += 256) {
            int r = e >> 3, u = e & 7;
            CP_ASYNC16(skb + (r * ST) * 2 + u * 16, Kg + r * 128 + u * 16);
        }
        for (int e = tid; e < 512; e += 256) {
            int r = e >> 3, u = e & 7;
            CP_ASYNC16(svb + (r * ST) * 2 + u * 16, Vg + r * 2048 + u * 16);
        }
        CP_COMMIT();
        CP_WAIT0();
        __syncthreads();

        float accS[8][4];
#pragma unroll
        for (int nf = 0; nf < 8; nf++)
#pragma unroll
            for (int e = 0; e < 4; e++) accS[nf][e] = 0.f;

        const uint32_t kb = skb + b_lane;
#pragma unroll
        for (int ks = 0; ks < 4; ks++) {
            const uint32_t kofs = ks * 32;
#pragma unroll
            for (int pf = 0; pf < 4; pf++) {
                uint32_t b0, b1, b2, b3;
                LDSM_X4(b0, b1, b2, b3, kb + pf * 16 * ST * 2 + kofs);
                MMA_F16(accS[2*pf][0], accS[2*pf][1], accS[2*pf][2], accS[2*pf][3],
                        qf[ks][0], qf[ks][1], qf[ks][2], qf[ks][3], b0, b1);
                MMA_F16(accS[2*pf+1][0], accS[2*pf+1][1], accS[2*pf+1][2], accS[2*pf+1][3],
                        qf[ks][0], qf[ks][1], qf[ks][2], qf[ks][3], b2, b3);
            }
        }

        float cmax[2] = {-1e30f, -1e30f};
#pragma unroll
        for (int nf = 0; nf < 8; nf++) {
            cmax[0] = fmaxf(cmax[0], fmaxf(accS[nf][0], accS[nf][1]));
            cmax[1] = fmaxf(cmax[1], fmaxf(accS[nf][2], accS[nf][3]));
        }
#pragma unroll
        for (int o = 1; o <= 2; o <<= 1) {
            cmax[0] = fmaxf(cmax[0], __shfl_xor_sync(0xffffffffu, cmax[0], o));
            cmax[1] = fmaxf(cmax[1], __shfl_xor_sync(0xffffffffu, cmax[1], o));
        }
        float mn0 = fmaxf(m_run[0], cmax[0]);
        float mn1 = fmaxf(m_run[1], cmax[1]);
        float sc0 = __expf(m_run[0] - mn0);
        float sc1 = __expf(m_run[1] - mn1);
        m_run[0] = mn0; m_run[1] = mn1;

        float psum[2] = {0.f, 0.f};
#pragma unroll
        for (int nf = 0; nf < 8; nf++) {
            accS[nf][0] = __expf(accS[nf][0] - mn0);
            accS[nf][1] = __expf(accS[nf][1] - mn0);
            accS[nf][2] = __expf(accS[nf][2] - mn1);
            accS[nf][3] = __expf(accS[nf][3] - mn1);
            psum[0] += accS[nf][0] + accS[nf][1];
            psum[1] += accS[nf][2] + accS[nf][3];
        }
        l_t[0] = l_t[0] * sc0 + psum[0];
        l_t[1] = l_t[1] * sc1 + psum[1];

        if (t == 0) { sScale[jr] = sc0; sScale[jr + 8] = sc1; }
#pragma unroll
        for (int nf = 0; nf < 8; nf++) {
            int ic = nf * 8 + 2 * t;
            *(__half2*)&sP[jr * ST + ic]       = __floats2half2_rn(accS[nf][0], accS[nf][1]);
            *(__half2*)&sP[(jr + 8) * ST + ic] = __floats2half2_rn(accS[nf][2], accS[nf][3]);
        }
        __syncthreads();

#pragma unroll
        for (int nf = 0; nf < 4; nf++) {
            float s0 = sScale[wj * 32 + nf * 8 + 2 * t];
            float s1 = sScale[wj * 32 + nf * 8 + 2 * t + 1];
#pragma unroll
            for (int mf = 0; mf < 2; mf++) {
                accO[mf][nf][0] *= s0; accO[mf][nf][1] *= s1;
                accO[mf][nf][2] *= s0; accO[mf][nf][3] *= s1;
            }
        }
        const uint32_t va = svb + (wc * 32 * ST) * 2 + a_lane;
        const uint32_t pb = spb + (wj * 32 * ST) * 2 + b_lane;
#pragma unroll
        for (int ks = 0; ks < 4; ks++) {
            const uint32_t kofs = ks * 32;
            uint32_t af[2][4];
#pragma unroll
            for (int mf = 0; mf < 2; mf++)
                LDSM_X4(af[mf][0], af[mf][1], af[mf][2], af[mf][3],
                        va + mf * 16 * ST * 2 + kofs);
#pragma unroll
            for (int pf = 0; pf < 2; pf++) {
                uint32_t b0, b1, b2, b3;
                LDSM_X4(b0, b1, b2, b3, pb + pf * 16 * ST * 2 + kofs);
#pragma unroll
                for (int mf = 0; mf < 2; mf++) {
                    MMA_F16(accO[mf][2*pf][0], accO[mf][2*pf][1], accO[mf][2*pf][2], accO[mf][2*pf][3],
                            af[mf][0], af[mf][1], af[mf][2], af[mf][3], b0, b1);
                    MMA_F16(accO[mf][2*pf+1][0], accO[mf][2*pf+1][1], accO[mf][2*pf+1][2], accO[mf][2*pf+1][3],
                            af[mf][0], af[mf][1], af[mf][2], af[mf][3], b2, b3);
                }
            }
        }
        __syncthreads();
    }

#pragma unroll
    for (int o = 1; o <= 2; o <<= 1) {
        l_t[0] += __shfl_xor_sync(0xffffffffu, l_t[0], o);
        l_t[1] += __shfl_xor_sync(0xffffffffu, l_t[1], o);
    }
    if (t == 0) {
        sScale[jr]     = 1.f / l_t[0];
        sScale[jr + 8] = 1.f / l_t[1];
    }
    __syncthreads();

    const int n = m >> 2, hh = m & 3;
    const int b = n / 9, rem = n % 9;
    const int wh = rem / 3, ww = rem % 3;
#pragma unroll
    for (int nf = 0; nf < 4; nf++) {
#pragma unroll
        for (int e = 0; e < 2; e++) {
            const int jl = wj * 32 + nf * 8 + 2 * t + e;
            const float inv = sScale[jl];
            const int j = jt * 128 + jl;
            const int h = wh * 32 + (j >> 5), w = ww * 32 + (j & 31);
            __half* dst = g_ocl + (((size_t)b * 98 + h + 1) * 98 + (w + 1)) * 256 + hh * 64;
#pragma unroll
            for (int mf = 0; mf < 2; mf++) {
                const int c0 = wc * 32 + mf * 16 + g;
                dst[c0]     = __float2half_rn(accO[mf][nf][0 + e] * inv);
                dst[c0 + 8] = __float2half_rn(accO[mf][nf][2 + e] * inv);
            }
        }
    }
}

// ===========================================================================
extern "C" void kernel_launch(void* const* d_in, const int* in_sizes, int n_in,
                              void* d_out, int out_size)
{
    (void)in_sizes; (void)n_in; (void)out_size;
    const float* x  = (const float*)d_in[0];
    const float* W1 = (const float*)d_in[1];
    const float* b1 = (const float*)d_in[2];
    const float* W2 = (const float*)d_in[3];
    const float* b2 = (const float*)d_in[4];
    float* out = (float*)d_out;

    const int CONV_SMEM = 2 * (9 * 128 * 64 + 340 * 64);   // 190976 B
    cudaFuncSetAttribute(conv_mma_kernel<512, 768, 0>,
                         cudaFuncAttributeMaxDynamicSharedMemorySize, CONV_SMEM);
    cudaFuncSetAttribute(conv_mma_kernel<256, 512, 1>,
                         cudaFuncAttributeMaxDynamicSharedMemorySize, CONV_SMEM);

    const int ATTN_SMEM = (128 + 64 + 64 + 128) * 72 * 2 + 128 * 4;  // 55808 B
    cudaFuncSetAttribute(fused_attn_kernel,
                         cudaFuncAttributeMaxDynamicSharedMemorySize, ATTN_SMEM);

    // pack inputs / weights (fp16)
    fill_border_kernel<512><<<(2 * 388 * 64 + 255) / 256, 256>>>();
    fill_border_kernel<256><<<(2 * 388 * 32 + 255) / 256, 256>>>();
    pack_cl_kernel<<<dim3(96, 16, 2), 256>>>(x);
    repack_w_kernel<768, 512, 0><<<(9 * 768 * 512 + 255) / 256, 256>>>(W1);
    repack_w_kernel<512, 256, 1><<<(9 * 512 * 256 + 255) / 256, 256>>>(W2);

    // conv1 + ReLU -> packed Q/K/V (fp16 mma, halo-resident)
    conv_mma_kernel<512, 768, 0><<<dim3(72, 6), 256, CONV_SMEM>>>(b1, nullptr, nullptr);

    // fused attention -> g_ocl (fp16 channels-last conv2 input)
    fused_attn_kernel<<<dim3(8, 72), 256, ATTN_SMEM>>>();

    // conv2 + residual (fp16 mma, halo-resident, fp32 epilogue)
    conv_mma_kernel<256, 512, 1><<<dim3(72, 4), 256, CONV_SMEM>>>(b2, x, out);
}

// round 10
// speedup vs baseline: 10.3334x; 1.0182x over previous
#include <cuda_runtime.h>
#include <cuda_fp16.h>
#include <math.h>
#include <stdint.h>

// ===========================================================================
// LocalAttention on sm_100 (portable PTX; mma.sync f16.f32 + ldmatrix):
//   conv3x3(512->768)+ReLU  -> halo-resident fp16 implicit GEMM, packs Q/K/V
//   fused flash-style windowed attention (fp16, K/V double-buffered)
//   conv3x3(256->512)+residual -> halo-resident fp16 implicit GEMM
// ===========================================================================

// ------------------------------- scratch ----------------------------------
__device__ __half g_kt [72 * 1024 * 64];      // K: [m][i][c]
__device__ __half g_qt [72 * 1024 * 64];      // Q: [m][j][c] (pre-scaled 1/8)
__device__ __half g_v  [72 * 64 * 1024];      // V: [m][c][i]
__device__ __half g_xcl[2 * 98 * 98 * 512];   // padded channels-last input
__device__ __half g_ocl[2 * 98 * 98 * 256];   // padded channels-last attn out
__device__ __half g_w1p[9 * 768 * 512];       // W1 [s][co][ci]
__device__ __half g_w2p[9 * 512 * 256];       // W2 [s][co][ci]

// ------------------------------ helpers -----------------------------------
__device__ __forceinline__ uint32_t smem_u32(const void* p) {
    uint32_t a;
    asm("{ .reg .u64 t; cvta.to.shared.u64 t, %1; cvt.u32.u64 %0, t; }" : "=r"(a) : "l"(p));
    return a;
}

#define CP_ASYNC16(sm, gm) \
    asm volatile("cp.async.cg.shared.global [%0], [%1], 16;" :: "r"(sm), "l"(gm))
#define CP_COMMIT() asm volatile("cp.async.commit_group;" ::: "memory")
#define CP_WAIT1()  asm volatile("cp.async.wait_group 1;" ::: "memory")
#define CP_WAIT0()  asm volatile("cp.async.wait_group 0;" ::: "memory")

#define MMA_F16(c0,c1,c2,c3, a0,a1,a2,a3, b0,b1) \
    asm volatile("mma.sync.aligned.m16n8k16.row.col.f32.f16.f16.f32 " \
        "{%0,%1,%2,%3}, {%4,%5,%6,%7}, {%8,%9}, {%0,%1,%2,%3};" \
        : "+f"(c0), "+f"(c1), "+f"(c2), "+f"(c3) \
        : "r"(a0), "r"(a1), "r"(a2), "r"(a3), "r"(b0), "r"(b1))

#define LDSM_X4(r0,r1,r2,r3, a) \
    asm volatile("ldmatrix.sync.aligned.m8n8.x4.shared.b16 {%0,%1,%2,%3}, [%4];" \
        : "=r"(r0), "=r"(r1), "=r"(r2), "=r"(r3) : "r"(a))

// 64B rows (32 halves), 16B-unit XOR swizzle: conflict-free for ldmatrix
__device__ __forceinline__ uint32_t swz_addr(uint32_t base, int row, int seg) {
    return base + row * 64 + ((seg ^ ((row >> 1) & 3)) << 4);
}

// ===========================================================================
// Pack kernels (merged: fewer launches)
// ===========================================================================
__global__ void fill_border_all_kernel() {
    // part 0: g_xcl (C=512, 64 units/px), part 1: g_ocl (C=256, 32 units/px)
    int idx = blockIdx.x * 256 + threadIdx.x;
    const int N1 = 2 * 388 * 64;
    const int N2 = 2 * 388 * 32;
    __half* out;
    int un, C;
    if (idx < N1) { out = g_xcl; un = 64; C = 512; }
    else if (idx < N1 + N2) { idx -= N1; out = g_ocl; un = 32; C = 256; }
    else return;
    int u = idx % un;
    int cell = (idx / un) % 388;
    int b = idx / (388 * un);
    int h, w;
    if (cell < 98)        { h = 0;  w = cell; }
    else if (cell < 196)  { h = 97; w = cell - 98; }
    else if (cell < 292)  { h = cell - 196 + 1; w = 0; }
    else                  { h = cell - 292 + 1; w = 97; }
    uint4 z = make_uint4(0u, 0u, 0u, 0u);
    ((uint4*)&out[(((size_t)b * 98 + h) * 98 + w) * C])[u] = z;
}

__global__ __launch_bounds__(256) void pack_cl_kernel(const float* __restrict__ in) {
    __shared__ float s[32][97];
    const int h = blockIdx.x, cig = blockIdx.y, b = blockIdx.z;
    const int tid = threadIdx.x;
    for (int e = tid; e < 32 * 96; e += 256) {
        int ci = e / 96, w = e % 96;
        s[ci][w] = in[(((size_t)b * 512 + cig * 32 + ci) * 96 + h) * 96 + w];
    }
    __syncthreads();
    for (int e = tid; e < 96 * 32; e += 256) {
        int w = e >> 5, ci = e & 31;
        g_xcl[(((size_t)b * 98 + h + 1) * 98 + (w + 1)) * 512 + cig * 32 + ci] =
            __float2half_rn(s[ci][w]);
    }
}

__global__ void repack_w_all_kernel(const float* __restrict__ W1,
                                    const float* __restrict__ W2) {
    int idx = blockIdx.x * 256 + threadIdx.x;
    const int N1 = 9 * 768 * 512;
    const int N2 = 9 * 512 * 256;
    if (idx < N1) {
        int s = idx / (768 * 512);
        int rem = idx % (768 * 512);
        int co = rem / 512, ci = rem % 512;
        g_w1p[idx] = __float2half_rn(W1[((size_t)co * 512 + ci) * 9 + s]);
    } else if (idx < N1 + N2) {
        int e = idx - N1;
        int s = e / (512 * 256);
        int rem = e % (512 * 256);
        int co = rem / 256, ci = rem % 256;
        g_w2p[e] = __float2half_rn(W2[((size_t)co * 256 + ci) * 9 + s]);
    }
}

// ===========================================================================
// Halo-resident fp16 implicit-GEMM conv3x3 (unchanged from R9).
// CTA: D[128 co x 256 px(8x32)]; 8 warps (2M x 4N), warp tile 64co x 64px.
// Per 32-ci chunk: smem holds A[9][128][32] (all taps) + halo B[340][32]
// (10x34 pixels); MMA sweeps all 9 taps against the resident halo.
// ===========================================================================
template <int CIN, int COUT, int MODE>
__global__ void __launch_bounds__(256, 1)
conv_mma_kernel(const float* __restrict__ bias,
                const float* __restrict__ resid,
                float* __restrict__ out)
{
    constexpr int NCH   = CIN / 32;
    constexpr int ABYT  = 9 * 128 * 64;      // 73728 B per buffer
    constexpr int BBYT  = 340 * 64;          // 21760 B per buffer
    constexpr int BUFB  = ABYT + BBYT;

    const __half* __restrict__ Wp  = (MODE == 0) ? g_w1p : g_w2p;
    const __half* __restrict__ xcl = (MODE == 0) ? g_xcl : g_ocl;
    const int XC = (MODE == 0) ? 512 : 256;

    extern __shared__ __half smh[];
    const uint32_t sb = smem_u32(smh);

    const int tid  = threadIdx.x;
    const int wid  = tid >> 5;
    const int lane = tid & 31;
    const int g = lane >> 2;
    const int t = lane & 3;
    const int wm = wid >> 2;
    const int wn = wid & 3;
    const int quad = lane >> 3, rin = lane & 7;

    const int a_rin = (quad & 1) * 8 + rin;
    const int a_sb  = quad >> 1;
    const int b_rin = (quad >> 1) * 8 + rin;
    const int b_sb  = quad & 1;

    const int pt = blockIdx.x;
    const int b  = pt / 36;
    const int r  = pt % 36;
    const int h0 = (r / 3) * 8;
    const int w0 = (r % 3) * 32;
    const int co0 = blockIdx.y * 128;

    int pxc[4];
#pragma unroll
    for (int pf = 0; pf < 4; pf++) {
        int n0 = wn * 64 + pf * 16;
        pxc[pf] = (n0 >> 5) * 34 + (n0 & 31);
    }

    auto load_stage = [&](int ch, int buf) {
        const int ci0 = ch * 32;
        const uint32_t base = sb + buf * BUFB;
#pragma unroll
        for (int i = 0; i < 18; i++) {
            int e = tid + i * 256;
            int row = e >> 2, seg = e & 3;
            int s = row >> 7, cor = row & 127;
            const char* ga = (const char*)
                (Wp + ((size_t)s * COUT + co0 + cor) * CIN + ci0) + seg * 16;
            CP_ASYNC16(swz_addr(base, row, seg), ga);
        }
#pragma unroll
        for (int i = 0; i < 6; i++) {
            int e = tid + i * 256;
            if (e < 1360) {
                int row = e >> 2, seg = e & 3;
                int hr = row / 34, wc = row % 34;
                const char* gb = (const char*)
                    (xcl + (((size_t)(b * 98 + h0 + hr)) * 98 + (w0 + wc)) * XC + ci0) + seg * 16;
                CP_ASYNC16(swz_addr(base + ABYT, row, seg), gb);
            }
        }
        CP_COMMIT();
    };

    float acc[4][8][4];
#pragma unroll
    for (int mf = 0; mf < 4; mf++)
#pragma unroll
        for (int nf = 0; nf < 8; nf++)
#pragma unroll
            for (int e = 0; e < 4; e++) acc[mf][nf][e] = 0.f;

    load_stage(0, 0);

    for (int ch = 0; ch < NCH; ++ch) {
        const int buf = ch & 1;
        if (ch + 1 < NCH) { load_stage(ch + 1, buf ^ 1); CP_WAIT1(); }
        else              { CP_WAIT0(); }
        __syncthreads();

        const uint32_t abase = sb + buf * BUFB;
        const uint32_t bbase = abase + ABYT;
        const int arow0 = wm * 64 + a_rin;

#pragma unroll 1
        for (int s = 0; s < 9; s++) {
            const int kh = s / 3, kw = s % 3;
            const int hb = kh * 34 + kw + b_rin;
            const int ab = s * 128 + arow0;
#pragma unroll
            for (int ks = 0; ks < 2; ks++) {
                const int bseg = ks * 2 + b_sb;
                const int aseg = ks * 2 + a_sb;
                uint32_t bf[4][4];
#pragma unroll
                for (int pf = 0; pf < 4; pf++) {
                    int hrow = hb + pxc[pf];
                    LDSM_X4(bf[pf][0], bf[pf][1], bf[pf][2], bf[pf][3],
                            swz_addr(bbase, hrow, bseg));
                }
#pragma unroll
                for (int mf = 0; mf < 4; mf++) {
                    uint32_t a0, a1, a2, a3;
                    LDSM_X4(a0, a1, a2, a3, swz_addr(abase, ab + mf * 16, aseg));
#pragma unroll
                    for (int pf = 0; pf < 4; pf++) {
                        MMA_F16(acc[mf][2*pf][0], acc[mf][2*pf][1], acc[mf][2*pf][2], acc[mf][2*pf][3],
                                a0, a1, a2, a3, bf[pf][0], bf[pf][1]);
                        MMA_F16(acc[mf][2*pf+1][0], acc[mf][2*pf+1][1], acc[mf][2*pf+1][2], acc[mf][2*pf+1][3],
                                a0, a1, a2, a3, bf[pf][2], bf[pf][3]);
                    }
                }
            }
        }
        __syncthreads();
    }

    // ----------------------------- epilogue -------------------------------
#pragma unroll
    for (int mf = 0; mf < 4; mf++) {
#pragma unroll
        for (int half8 = 0; half8 < 2; half8++) {
            const int co_g = co0 + wm * 64 + mf * 16 + g + half8 * 8;
            const float bv = __ldg(&bias[co_g]);
            if (MODE == 0) {
                const int part = co_g >> 8;          // 0=K 1=V 2=Q
                const int hh   = (co_g >> 6) & 3;
                const int cc   = co_g & 63;
                const int mm   = ((b * 9 + (h0 >> 5) * 3 + (w0 >> 5)) << 2) + hh;
                const float qs = (part == 2) ? 0.125f : 1.0f;
#pragma unroll
                for (int nf = 0; nf < 8; nf++) {
                    const int px0 = wn * 64 + nf * 8 + 2 * t;
                    float v0 = qs * fmaxf(acc[mf][nf][half8 * 2 + 0] + bv, 0.f);
                    float v1 = qs * fmaxf(acc[mf][nf][half8 * 2 + 1] + bv, 0.f);
                    const int l0 = ((h0 & 31) + (px0 >> 5)) * 32 + (px0 & 31);
                    if (part == 1) {
                        __half2* dst = (__half2*)(g_v + ((size_t)(mm * 64 + cc)) * 1024 + l0);
                        *dst = __floats2half2_rn(v0, v1);
                    } else {
                        __half* dq = (part ? g_qt : g_kt) + ((size_t)mm * 1024 + l0) * 64 + cc;
                        dq[0]  = __float2half_rn(v0);
                        dq[64] = __float2half_rn(v1);
                    }
                }
            } else {
#pragma unroll
                for (int nf = 0; nf < 8; nf++) {
                    const int px0 = wn * 64 + nf * 8 + 2 * t;
                    const int h = h0 + (px0 >> 5), w = w0 + (px0 & 31);
                    const size_t idx = (((size_t)(b * 512 + co_g) * 96) + h) * 96 + w;
                    float2 rv = *(const float2*)(resid + idx);
                    float2 v;
                    v.x = rv.x + bv + acc[mf][nf][half8 * 2 + 0];
                    v.y = rv.y + bv + acc[mf][nf][half8 * 2 + 1];
                    *(float2*)(out + idx) = v;
                }
            }
        }
    }
}

// ===========================================================================
// Fused flash-style attention, fp16 + ldmatrix, K/V DOUBLE-BUFFERED.
// CTA = (m, 128-j tile). 256 threads, 8 warps; 16 x 64-i chunks.
// smem: sQ[128][72], sK[2][64][72], sV[2][64][72], sP[128][72] -> 74.2 KB, occ 2
// ===========================================================================
__global__ void __launch_bounds__(256, 2) fused_attn_kernel()
{
    constexpr int ST = 72;
    constexpr uint32_t KVB = 64 * ST * 2;      // bytes per K (or V) buffer
    extern __shared__ __half sh[];
    __half* sQ = sh;                            // [128][72]
    __half* sK = sQ + 128 * ST;                 // [2][64][72]
    __half* sV = sK + 2 * 64 * ST;              // [2][64][72]
    __half* sP = sV + 2 * 64 * ST;              // [128][72]
    float* sScale = (float*)(sP + 128 * ST);    // [128]

    const int m  = blockIdx.y;
    const int jt = blockIdx.x;
    const int tid = threadIdx.x, wid = tid >> 5, lane = tid & 31;
    const int g = lane >> 2, t = lane & 3;
    const int wc = wid >> 2;
    const int wj = wid & 3;
    const uint32_t quad = lane >> 3, rin = lane & 7;
    const uint32_t a_lane = (((quad & 1) * 8 + rin) * ST + (quad >> 1) * 8) * 2;
    const uint32_t b_lane = (((quad >> 1) * 8 + rin) * ST + (quad & 1) * 8) * 2;

    const uint32_t sqb = smem_u32(sQ), skb = smem_u32(sK);
    const uint32_t svb = smem_u32(sV), spb = smem_u32(sP);

    auto load_kv = [&](int ch, int buf) {
        const int i0 = ch * 64;
        const char* Kg = (const char*)(g_kt + ((size_t)m * 1024 + i0) * 64);
        const char* Vg = (const char*)(g_v + (size_t)m * 64 * 1024 + i0);
        const uint32_t kb0 = skb + buf * KVB;
        const uint32_t vb0 = svb + buf * KVB;
        for (int e = tid; e < 512; e += 256) {
            int r = e >> 3, u = e & 7;
            CP_ASYNC16(kb0 + (r * ST) * 2 + u * 16, Kg + r * 128 + u * 16);
        }
        for (int e = tid; e < 512; e += 256) {
            int r = e >> 3, u = e & 7;
            CP_ASYNC16(vb0 + (r * ST) * 2 + u * 16, Vg + r * 2048 + u * 16);
        }
        CP_COMMIT();
    };

    // ---- Q loads (group 0), KV chunk 0 (group 1) ----
    {
        const char* Qg = (const char*)(g_qt + ((size_t)m * 1024 + jt * 128) * 64);
        for (int e = tid; e < 1024; e += 256) {
            int r = e >> 3, u = e & 7;
            CP_ASYNC16(sqb + (r * ST) * 2 + u * 16, Qg + r * 128 + u * 16);
        }
        CP_COMMIT();
    }
    load_kv(0, 0);
    CP_WAIT1();               // Q ready
    __syncthreads();

    uint32_t qf[4][4];
    {
        const uint32_t qa = sqb + (wid * 16 * ST) * 2 + a_lane;
#pragma unroll
        for (int ks = 0; ks < 4; ks++)
            LDSM_X4(qf[ks][0], qf[ks][1], qf[ks][2], qf[ks][3], qa + ks * 32);
    }

    float accO[2][4][4];
#pragma unroll
    for (int mf = 0; mf < 2; mf++)
#pragma unroll
        for (int nf = 0; nf < 4; nf++)
#pragma unroll
            for (int e = 0; e < 4; e++) accO[mf][nf][e] = 0.f;

    float m_run[2] = {-1e30f, -1e30f};
    float l_t[2]   = {0.f, 0.f};
    const int jr = wid * 16 + g;

    for (int ch = 0; ch < 16; ch++) {
        const int buf = ch & 1;
        if (ch + 1 < 16) { load_kv(ch + 1, buf ^ 1); CP_WAIT1(); }
        else             { CP_WAIT0(); }
        __syncthreads();

        // ---- QK: S[16 j][64 i] per warp ----
        float accS[8][4];
#pragma unroll
        for (int nf = 0; nf < 8; nf++)
#pragma unroll
            for (int e = 0; e < 4; e++) accS[nf][e] = 0.f;

        const uint32_t kb = skb + buf * KVB + b_lane;
#pragma unroll
        for (int ks = 0; ks < 4; ks++) {
            const uint32_t kofs = ks * 32;
#pragma unroll
            for (int pf = 0; pf < 4; pf++) {
                uint32_t b0, b1, b2, b3;
                LDSM_X4(b0, b1, b2, b3, kb + pf * 16 * ST * 2 + kofs);
                MMA_F16(accS[2*pf][0], accS[2*pf][1], accS[2*pf][2], accS[2*pf][3],
                        qf[ks][0], qf[ks][1], qf[ks][2], qf[ks][3], b0, b1);
                MMA_F16(accS[2*pf+1][0], accS[2*pf+1][1], accS[2*pf+1][2], accS[2*pf+1][3],
                        qf[ks][0], qf[ks][1], qf[ks][2], qf[ks][3], b2, b3);
            }
        }

        // ---- online softmax over i (cols), rows jr / jr+8 ----
        float cmax[2] = {-1e30f, -1e30f};
#pragma unroll
        for (int nf = 0; nf < 8; nf++) {
            cmax[0] = fmaxf(cmax[0], fmaxf(accS[nf][0], accS[nf][1]));
            cmax[1] = fmaxf(cmax[1], fmaxf(accS[nf][2], accS[nf][3]));
        }
#pragma unroll
        for (int o = 1; o <= 2; o <<= 1) {
            cmax[0] = fmaxf(cmax[0], __shfl_xor_sync(0xffffffffu, cmax[0], o));
            cmax[1] = fmaxf(cmax[1], __shfl_xor_sync(0xffffffffu, cmax[1], o));
        }
        float mn0 = fmaxf(m_run[0], cmax[0]);
        float mn1 = fmaxf(m_run[1], cmax[1]);
        float sc0 = __expf(m_run[0] - mn0);
        float sc1 = __expf(m_run[1] - mn1);
        m_run[0] = mn0; m_run[1] = mn1;

        float psum[2] = {0.f, 0.f};
#pragma unroll
        for (int nf = 0; nf < 8; nf++) {
            accS[nf][0] = __expf(accS[nf][0] - mn0);
            accS[nf][1] = __expf(accS[nf][1] - mn0);
            accS[nf][2] = __expf(accS[nf][2] - mn1);
            accS[nf][3] = __expf(accS[nf][3] - mn1);
            psum[0] += accS[nf][0] + accS[nf][1];
            psum[1] += accS[nf][2] + accS[nf][3];
        }
        l_t[0] = l_t[0] * sc0 + psum[0];
        l_t[1] = l_t[1] * sc1 + psum[1];

        if (t == 0) { sScale[jr] = sc0; sScale[jr + 8] = sc1; }
#pragma unroll
        for (int nf = 0; nf < 8; nf++) {
            int ic = nf * 8 + 2 * t;
            *(__half2*)&sP[jr * ST + ic]       = __floats2half2_rn(accS[nf][0], accS[nf][1]);
            *(__half2*)&sP[(jr + 8) * ST + ic] = __floats2half2_rn(accS[nf][2], accS[nf][3]);
        }
        __syncthreads();

        // ---- PV: O[32 c][32 j] per warp; rescale then accumulate ----
#pragma unroll
        for (int nf = 0; nf < 4; nf++) {
            float s0 = sScale[wj * 32 + nf * 8 + 2 * t];
            float s1 = sScale[wj * 32 + nf * 8 + 2 * t + 1];
#pragma unroll
            for (int mf = 0; mf < 2; mf++) {
                accO[mf][nf][0] *= s0; accO[mf][nf][1] *= s1;
                accO[mf][nf][2] *= s0; accO[mf][nf][3] *= s1;
            }
        }
        const uint32_t va = svb + buf * KVB + (wc * 32 * ST) * 2 + a_lane;
        const uint32_t pb = spb + (wj * 32 * ST) * 2 + b_lane;
#pragma unroll
        for (int ks = 0; ks < 4; ks++) {
            const uint32_t kofs = ks * 32;
            uint32_t af[2][4];
#pragma unroll
            for (int mf = 0; mf < 2; mf++)
                LDSM_X4(af[mf][0], af[mf][1], af[mf][2], af[mf][3],
                        va + mf * 16 * ST * 2 + kofs);
#pragma unroll
            for (int pf = 0; pf < 2; pf++) {
                uint32_t b0, b1, b2, b3;
                LDSM_X4(b0, b1, b2, b3, pb + pf * 16 * ST * 2 + kofs);
#pragma unroll
                for (int mf = 0; mf < 2; mf++) {
                    MMA_F16(accO[mf][2*pf][0], accO[mf][2*pf][1], accO[mf][2*pf][2], accO[mf][2*pf][3],
                            af[mf][0], af[mf][1], af[mf][2], af[mf][3], b0, b1);
                    MMA_F16(accO[mf][2*pf+1][0], accO[mf][2*pf+1][1], accO[mf][2*pf+1][2], accO[mf][2*pf+1][3],
                            af[mf][0], af[mf][1], af[mf][2], af[mf][3], b2, b3);
                }
            }
        }
        __syncthreads();
    }

    // ---- finalize: 1/l per row, broadcast, write g_ocl ----
#pragma unroll
    for (int o = 1; o <= 2; o <<= 1) {
        l_t[0] += __shfl_xor_sync(0xffffffffu, l_t[0], o);
        l_t[1] += __shfl_xor_sync(0xffffffffu, l_t[1], o);
    }
    if (t == 0) {
        sScale[jr]     = 1.f / l_t[0];
        sScale[jr + 8] = 1.f / l_t[1];
    }
    __syncthreads();

    const int n = m >> 2, hh = m & 3;
    const int b = n / 9, rem = n % 9;
    const int wh = rem / 3, ww = rem % 3;
#pragma unroll
    for (int nf = 0; nf < 4; nf++) {
#pragma unroll
        for (int e = 0; e < 2; e++) {
            const int jl = wj * 32 + nf * 8 + 2 * t + e;
            const float inv = sScale[jl];
            const int j = jt * 128 + jl;
            const int h = wh * 32 + (j >> 5), w = ww * 32 + (j & 31);
            __half* dst = g_ocl + (((size_t)b * 98 + h + 1) * 98 + (w + 1)) * 256 + hh * 64;
#pragma unroll
            for (int mf = 0; mf < 2; mf++) {
                const int c0 = wc * 32 + mf * 16 + g;
                dst[c0]     = __float2half_rn(accO[mf][nf][0 + e] * inv);
                dst[c0 + 8] = __float2half_rn(accO[mf][nf][2 + e] * inv);
            }
        }
    }
}

// ===========================================================================
extern "C" void kernel_launch(void* const* d_in, const int* in_sizes, int n_in,
                              void* d_out, int out_size)
{
    (void)in_sizes; (void)n_in; (void)out_size;
    const float* x  = (const float*)d_in[0];
    const float* W1 = (const float*)d_in[1];
    const float* b1 = (const float*)d_in[2];
    const float* W2 = (const float*)d_in[3];
    const float* b2 = (const float*)d_in[4];
    float* out = (float*)d_out;

    const int CONV_SMEM = 2 * (9 * 128 * 64 + 340 * 64);   // 190976 B
    cudaFuncSetAttribute(conv_mma_kernel<512, 768, 0>,
                         cudaFuncAttributeMaxDynamicSharedMemorySize, CONV_SMEM);
    cudaFuncSetAttribute(conv_mma_kernel<256, 512, 1>,
                         cudaFuncAttributeMaxDynamicSharedMemorySize, CONV_SMEM);

    const int ATTN_SMEM = (128 + 2 * 64 + 2 * 64 + 128) * 72 * 2 + 128 * 4;  // 74240 B
    cudaFuncSetAttribute(fused_attn_kernel,
                         cudaFuncAttributeMaxDynamicSharedMemorySize, ATTN_SMEM);

    // packs (merged launches)
    const int FB_TOTAL = 2 * 388 * 64 + 2 * 388 * 32;
    fill_border_all_kernel<<<(FB_TOTAL + 255) / 256, 256>>>();
    pack_cl_kernel<<<dim3(96, 16, 2), 256>>>(x);
    const int RW_TOTAL = 9 * 768 * 512 + 9 * 512 * 256;
    repack_w_all_kernel<<<(RW_TOTAL + 255) / 256, 256>>>(W1, W2);

    // conv1 + ReLU -> packed Q/K/V (fp16 mma, halo-resident)
    conv_mma_kernel<512, 768, 0><<<dim3(72, 6), 256, CONV_SMEM>>>(b1, nullptr, nullptr);

    // fused attention -> g_ocl (fp16 channels-last conv2 input)
    fused_attn_kernel<<<dim3(8, 72), 256, ATTN_SMEM>>>();

    // conv2 + residual (fp16 mma, halo-resident, fp32 epilogue)
    conv_mma_kernel<256, 512, 1><<<dim3(72, 4), 256, CONV_SMEM>>>(b2, x, out);
}